// round 5
// baseline (speedup 1.0000x reference)
#include <cuda_runtime.h>
#include <cstdint>
#include <cstddef>
#include <math_constants.h>

// ---------------------------------------------------------------------------
// Problem constants (B=1)
// ---------------------------------------------------------------------------
#define S_LEN 2048
#define H_DIM 4096
#define NHEAD 32
#define NKV   8
#define HD    128
#define I_DIM 11008
#define NEGF  (-3.4028234663852886e38f)   // jnp.finfo(float32).min

// ---------------------------------------------------------------------------
// Scratch (static device globals -- no allocation allowed)
// ---------------------------------------------------------------------------
__device__ float g_concat[(size_t)S_LEN * 2 * H_DIM];
__device__ float g_x     [(size_t)S_LEN * H_DIM];
__device__ float g_h     [(size_t)S_LEN * H_DIM];
__device__ float g_q     [(size_t)S_LEN * NHEAD * HD];   // pre-rope
__device__ float g_k     [(size_t)S_LEN * NKV * HD];     // pre-rope
__device__ float g_v     [(size_t)S_LEN * NKV * HD];
__device__ float g_q2    [(size_t)S_LEN * NHEAD * HD];   // post-rope
__device__ float g_k2    [(size_t)S_LEN * NKV * HD];     // post-rope
__device__ float g_cos   [(size_t)S_LEN * HD];
__device__ float g_sin   [(size_t)S_LEN * HD];
__device__ float g_attno [(size_t)S_LEN * NHEAD * HD];
__device__ float g_x2    [(size_t)S_LEN * H_DIM];
__device__ float g_h2    [(size_t)S_LEN * H_DIM];
__device__ float g_gate  [(size_t)S_LEN * I_DIM];
__device__ float g_act   [(size_t)S_LEN * I_DIM];
__device__ float g_scores[(size_t)NHEAD * S_LEN * S_LEN]; // 512MB

// ---------------------------------------------------------------------------
// warp dot of two contiguous vectors (K % 128 == 0)
// ---------------------------------------------------------------------------
__device__ __forceinline__ float warp_dot(const float* __restrict__ a,
                                          const float* __restrict__ b, int K)
{
    int lane = threadIdx.x & 31;
    const float4* a4 = (const float4*)a;
    const float4* b4 = (const float4*)b;
    float s = 0.f;
    for (int i = lane; i < (K >> 2); i += 32) {
        float4 x = a4[i], y = b4[i];
        s += x.x * y.x + x.y * y.y + x.z * y.z + x.w * y.w;
    }
#pragma unroll
    for (int o = 16; o; o >>= 1) s += __shfl_xor_sync(0xffffffffu, s, o);
    return s;
}

// ---------------------------------------------------------------------------
// concat([inputs_embeds, hidden_states]) -> g_concat
// ---------------------------------------------------------------------------
__global__ void concat_kernel(const float* __restrict__ emb,
                              const float* __restrict__ hid)
{
    int t = blockIdx.x * 256 + threadIdx.x;
    int s  = t >> 11;
    int c4 = t & 2047;
    float4 v;
    if (c4 < 1024) v = ((const float4*)emb)[(size_t)s * 1024 + c4];
    else           v = ((const float4*)hid)[(size_t)s * 1024 + (c4 - 1024)];
    ((float4*)g_concat)[t] = v;
}

// ---------------------------------------------------------------------------
// Tiled NT SGEMM (fc / gate / up / down only — exonerated by magnitude)
//   EPI 0: none | 1: +bias | 2: +resid | 3: *silu(resid)
// ---------------------------------------------------------------------------
template <int EPI>
__global__ void __launch_bounds__(256, 2)
sgemm_nt(const float* __restrict__ A, const float* __restrict__ B,
         float* __restrict__ C, int M, int N, int K,
         const float* __restrict__ bias, const float* __restrict__ resid)
{
    __shared__ float As[16][132];
    __shared__ float Bs[16][132];

    const int tid = threadIdx.x;
    const int tx = tid & 15;
    const int ty = tid >> 4;
    const int lrow = tid >> 2;
    const int lk = (tid & 3) << 2;

    const float* Ab = A + (size_t)blockIdx.y * 128 * K;
    const float* Bb = B + (size_t)blockIdx.x * 128 * K;

    float acc[8][8];
#pragma unroll
    for (int i = 0; i < 8; i++)
#pragma unroll
        for (int j = 0; j < 8; j++) acc[i][j] = 0.f;

    for (int k0 = 0; k0 < K; k0 += 16) {
        float4 a0 = *(const float4*)(Ab + (size_t)lrow * K + k0 + lk);
        float4 a1 = *(const float4*)(Ab + (size_t)(lrow + 64) * K + k0 + lk);
        float4 b0 = *(const float4*)(Bb + (size_t)lrow * K + k0 + lk);
        float4 b1 = *(const float4*)(Bb + (size_t)(lrow + 64) * K + k0 + lk);
        As[lk + 0][lrow] = a0.x; As[lk + 1][lrow] = a0.y;
        As[lk + 2][lrow] = a0.z; As[lk + 3][lrow] = a0.w;
        As[lk + 0][lrow + 64] = a1.x; As[lk + 1][lrow + 64] = a1.y;
        As[lk + 2][lrow + 64] = a1.z; As[lk + 3][lrow + 64] = a1.w;
        Bs[lk + 0][lrow] = b0.x; Bs[lk + 1][lrow] = b0.y;
        Bs[lk + 2][lrow] = b0.z; Bs[lk + 3][lrow] = b0.w;
        Bs[lk + 0][lrow + 64] = b1.x; Bs[lk + 1][lrow + 64] = b1.y;
        Bs[lk + 2][lrow + 64] = b1.z; Bs[lk + 3][lrow + 64] = b1.w;
        __syncthreads();

#pragma unroll
        for (int kk = 0; kk < 16; kk++) {
            float4 av0 = *(const float4*)&As[kk][ty * 8];
            float4 av1 = *(const float4*)&As[kk][ty * 8 + 4];
            float4 bv0 = *(const float4*)&Bs[kk][tx * 8];
            float4 bv1 = *(const float4*)&Bs[kk][tx * 8 + 4];
            float av[8] = {av0.x, av0.y, av0.z, av0.w, av1.x, av1.y, av1.z, av1.w};
            float bv[8] = {bv0.x, bv0.y, bv0.z, bv0.w, bv1.x, bv1.y, bv1.z, bv1.w};
#pragma unroll
            for (int i = 0; i < 8; i++)
#pragma unroll
                for (int j = 0; j < 8; j++) acc[i][j] += av[i] * bv[j];
        }
        __syncthreads();
    }

#pragma unroll
    for (int i = 0; i < 8; i++) {
        int row = blockIdx.y * 128 + ty * 8 + i;
#pragma unroll
        for (int j = 0; j < 8; j++) {
            int col = blockIdx.x * 128 + tx * 8 + j;
            float v = acc[i][j];
            if (EPI == 1) v += bias[col];
            if (EPI == 2) v += resid[(size_t)row * N + col];
            if (EPI == 3) {
                float g = resid[(size_t)row * N + col];
                v *= g / (1.f + expf(-g));
            }
            C[(size_t)row * N + col] = v;
        }
    }
}

// ---------------------------------------------------------------------------
// FRESH RMSNorm: block per row, scalar loads, shared-array reduce
// ---------------------------------------------------------------------------
__global__ void __launch_bounds__(256)
rmsnorm2_kernel(const float* __restrict__ x, const float* __restrict__ w,
                float* __restrict__ out)
{
    __shared__ float sh[256];
    int row = blockIdx.x;
    const float* xr = x + (size_t)row * H_DIM;
    float acc = 0.f;
    for (int c = threadIdx.x; c < H_DIM; c += 256) {
        float v = xr[c];
        acc += v * v;
    }
    sh[threadIdx.x] = acc;
    __syncthreads();
    for (int s2 = 128; s2 > 0; s2 >>= 1) {
        if (threadIdx.x < s2) sh[threadIdx.x] += sh[threadIdx.x + s2];
        __syncthreads();
    }
    float r = rsqrtf(sh[0] / (float)H_DIM + 1e-6f);
    for (int c = threadIdx.x; c < H_DIM; c += 256)
        out[(size_t)row * H_DIM + c] = xr[c] * r * w[c];
}

// ---------------------------------------------------------------------------
// NAIVE QKV projection: one warp per output element (fresh in r4, kept)
// ---------------------------------------------------------------------------
__global__ void __launch_bounds__(256)
qkv_naive(const float* __restrict__ qw, const float* __restrict__ kw,
          const float* __restrict__ vw)
{
    int w = (blockIdx.x * 256 + threadIdx.x) >> 5;
    int s   = w / 6144;
    int col = w % 6144;
    const float* hrow = g_h + (size_t)s * H_DIM;
    int lane = threadIdx.x & 31;

    if (col < 4096) {
        float r = warp_dot(hrow, qw + (size_t)col * H_DIM, H_DIM);
        if (lane == 0) g_q[(size_t)s * 4096 + col] = r;
    } else if (col < 5120) {
        int c = col - 4096;
        float r = warp_dot(hrow, kw + (size_t)c * H_DIM, H_DIM);
        if (lane == 0) g_k[(size_t)s * 1024 + c] = r;
    } else {
        int c = col - 5120;
        float r = warp_dot(hrow, vw + (size_t)c * H_DIM, H_DIM);
        if (lane == 0) g_v[(size_t)s * 1024 + c] = r;
    }
}

// ---------------------------------------------------------------------------
// FRESH RoPE stage 1: build cos/sin caches exactly like _rope_cache.
// inv_freq[j] = 1 / 10000^(2j/128); emb[d] = freqs[d<64 ? d : d-64].
// position dtype-robust (int32 proven by r1->r2 experiment; int64 fallback).
// ---------------------------------------------------------------------------
__global__ void rope_cache_kernel(const int* __restrict__ pos32)
{
    int t = blockIdx.x * 256 + threadIdx.x;     // s*128 + d, total 2048*128
    int s = t >> 7;
    int d = t & 127;
    long long pv;
    if (pos32[1] == 1) pv = (long long)pos32[s];
    else               pv = ((const long long*)pos32)[s];
    int j = (d < 64) ? d : d - 64;
    float invf = 1.0f / powf(10000.0f, (float)(2 * j) / 128.0f);
    float ang = (float)pv * invf;
    g_cos[t] = cosf(ang);
    g_sin[t] = sinf(ang);
}

// ---------------------------------------------------------------------------
// FRESH RoPE stage 2: literal q*cos + rotate_half(q)*sin, OUT-OF-PLACE.
// rotate_half(x)[d] = (d<64) ? -x[d+64] : x[d-64].
// Covers q (2048x4096) then k (2048x1024).
// ---------------------------------------------------------------------------
__global__ void rope_apply_kernel()
{
    int t = blockIdx.x * 256 + threadIdx.x;     // total 2048*5120
    int s = t / 5120;
    int c = t % 5120;
    const float* cs = g_cos + (size_t)s * HD;
    const float* sn = g_sin + (size_t)s * HD;
    if (c < 4096) {
        int d = c & 127;
        const float* qrow = g_q + (size_t)s * 4096;
        float rh = (d < 64) ? -qrow[c + 64] : qrow[c - 64];
        g_q2[(size_t)s * 4096 + c] = qrow[c] * cs[d] + rh * sn[d];
    } else {
        int cc = c - 4096;
        int d = cc & 127;
        const float* krow = g_k + (size_t)s * 1024;
        float rh = (d < 64) ? -krow[cc + 64] : krow[cc - 64];
        g_k2[(size_t)s * 1024 + cc] = krow[cc] * cs[d] + rh * sn[d];
    }
}

// ---------------------------------------------------------------------------
// FRESH scores: one thread per (h, q, k). Literal additive mask:
// scores = (q.k)/sqrt(128) + causal(NEG if k>q) + pad(NEG if amask<=0.5)
// GQA: q head h reads roped k head h/4 (jnp.repeat semantics).
// ---------------------------------------------------------------------------
__global__ void __launch_bounds__(256)
scores_kernel(const float* __restrict__ amask)
{
    size_t t = (size_t)blockIdx.x * 256 + threadIdx.x;  // ((h*2048+q)*2048+k)
    int k = (int)(t & 2047);
    int q = (int)((t >> 11) & 2047);
    int h = (int)(t >> 22);
    const float* qr = g_q2 + (size_t)q * 4096 + h * 128;
    const float* kr = g_k2 + (size_t)k * 1024 + (h >> 2) * 128;
    float dot = 0.f;
#pragma unroll 8
    for (int d = 0; d < 128; d++) dot += qr[d] * kr[d];
    float m = ((k > q) ? NEGF : 0.f) + ((amask[k] > 0.5f) ? 0.f : NEGF);
    g_scores[t] = dot * 0.08838834764831845f + m;
}

// ---------------------------------------------------------------------------
// FRESH softmax: one warp per (h, q) row, exact two-pass over k in [0, 2048).
// ---------------------------------------------------------------------------
__global__ void __launch_bounds__(256)
softmax2_kernel()
{
    int gw = (blockIdx.x * 256 + threadIdx.x) >> 5;   // h*2048 + q
    int lane = threadIdx.x & 31;
    float* row = g_scores + (size_t)gw * 2048;

    float m = -CUDART_INF_F;
    for (int k = lane; k < 2048; k += 32) m = fmaxf(m, row[k]);
#pragma unroll
    for (int o = 16; o; o >>= 1) m = fmaxf(m, __shfl_xor_sync(0xffffffffu, m, o));

    float sum = 0.f;
    for (int k = lane; k < 2048; k += 32) {
        float p = expf(row[k] - m);
        row[k] = p;
        sum += p;
    }
#pragma unroll
    for (int o = 16; o; o >>= 1) sum += __shfl_xor_sync(0xffffffffu, sum, o);
    float inv = 1.f / sum;
    for (int k = lane; k < 2048; k += 32) row[k] *= inv;
}

// ---------------------------------------------------------------------------
// NAIVE P @ V (fresh in r4, kept): warp per (h,q); lane owns float4 of d.
// Full k range [0,2048): masked probs are exactly 0 after softmax.
// ---------------------------------------------------------------------------
__global__ void __launch_bounds__(256)
pv_naive()
{
    int w = (blockIdx.x * 256 + threadIdx.x) >> 5;
    int lane = threadIdx.x & 31;
    int h = w >> 11;
    int q = w & 2047;

    const float* P = g_scores + ((size_t)h * S_LEN + q) * S_LEN;
    const float* V = g_v + (h >> 2) * HD + lane * 4;

    float4 acc = make_float4(0.f, 0.f, 0.f, 0.f);
    for (int k = 0; k <= q; k++) {
        float p = P[k];
        float4 v = *(const float4*)(V + (size_t)k * (NKV * HD));
        acc.x += p * v.x; acc.y += p * v.y;
        acc.z += p * v.z; acc.w += p * v.w;
    }
    *(float4*)(g_attno + (size_t)q * (NHEAD * HD) + h * HD + lane * 4) = acc;
}

// ---------------------------------------------------------------------------
// NAIVE O-proj + residual (fresh in r4, kept)
// ---------------------------------------------------------------------------
__global__ void __launch_bounds__(256)
o_naive(const float* __restrict__ ow)
{
    int w = (blockIdx.x * 256 + threadIdx.x) >> 5;
    int s = w >> 12;
    int n = w & 4095;
    float r = warp_dot(g_attno + (size_t)s * H_DIM, ow + (size_t)n * H_DIM, H_DIM);
    if ((threadIdx.x & 31) == 0)
        g_x2[(size_t)s * H_DIM + n] = r + g_x[(size_t)s * H_DIM + n];
}

// ---------------------------------------------------------------------------
// kernel_launch
// ---------------------------------------------------------------------------
extern "C" void kernel_launch(void* const* d_in, const int* in_sizes, int n_in,
                              void* d_out, int out_size)
{
    const float* hidden      = (const float*)d_in[0];
    const float* embeds      = (const float*)d_in[1];
    const float* amask       = (const float*)d_in[2];
    const float* fc_w        = (const float*)d_in[3];
    const float* fc_b        = (const float*)d_in[4];
    const float* in_norm_w   = (const float*)d_in[5];
    const float* q_w         = (const float*)d_in[6];
    const float* k_w         = (const float*)d_in[7];
    const float* v_w         = (const float*)d_in[8];
    const float* o_w         = (const float*)d_in[9];
    const float* post_norm_w = (const float*)d_in[10];
    const float* gate_w      = (const float*)d_in[11];
    const float* up_w        = (const float*)d_in[12];
    const float* down_w      = (const float*)d_in[13];
    const int* pos           = (const int*)d_in[14];
    float* out = (float*)d_out;

    void *pcat, *px, *ph, *px2, *ph2, *pgate, *pact;
    cudaGetSymbolAddress(&pcat, g_concat);
    cudaGetSymbolAddress(&px, g_x);
    cudaGetSymbolAddress(&ph, g_h);
    cudaGetSymbolAddress(&px2, g_x2);
    cudaGetSymbolAddress(&ph2, g_h2);
    cudaGetSymbolAddress(&pgate, g_gate);
    cudaGetSymbolAddress(&pact, g_act);

    // 1. concat
    concat_kernel<<<(S_LEN * 2048) / 256, 256>>>(embeds, hidden);

    // 2. fc
    sgemm_nt<1><<<dim3(H_DIM / 128, S_LEN / 128), 256>>>(
        (const float*)pcat, fc_w, (float*)px, S_LEN, H_DIM, 2 * H_DIM, fc_b, nullptr);

    // 3. rmsnorm1 (fresh)
    rmsnorm2_kernel<<<S_LEN, 256>>>((const float*)px, in_norm_w, (float*)ph);

    // 4. qkv (naive)
    qkv_naive<<<(S_LEN * 6144 * 32) / 256, 256>>>(q_w, k_w, v_w);

    // 5. RoPE (fresh, literal, out-of-place)
    rope_cache_kernel<<<(S_LEN * HD) / 256, 256>>>(pos);
    rope_apply_kernel<<<(S_LEN * 5120) / 256, 256>>>();

    // 6. scores (fresh naive) -> softmax (fresh) -> PV (naive)
    scores_kernel<<<(int)(((size_t)NHEAD * S_LEN * S_LEN) / 256), 256>>>(amask);
    softmax2_kernel<<<(NHEAD * S_LEN * 32) / 256, 256>>>();
    pv_naive<<<(NHEAD * S_LEN * 32) / 256, 256>>>();

    // 7. o-proj + residual (naive)
    o_naive<<<(S_LEN * H_DIM * 32) / 256, 256>>>(o_w);

    // 8. rmsnorm2 (fresh)
    rmsnorm2_kernel<<<S_LEN, 256>>>((const float*)px2, post_norm_w, (float*)ph2);

    // 9-11. MLP
    sgemm_nt<0><<<dim3(I_DIM / 128, S_LEN / 128), 256>>>(
        (const float*)ph2, gate_w, (float*)pgate, S_LEN, I_DIM, 4096, nullptr, nullptr);
    sgemm_nt<3><<<dim3(I_DIM / 128, S_LEN / 128), 256>>>(
        (const float*)ph2, up_w, (float*)pact, S_LEN, I_DIM, 4096, nullptr, (const float*)pgate);
    sgemm_nt<2><<<dim3(H_DIM / 128, S_LEN / 128), 256>>>(
        (const float*)pact, down_w, out, S_LEN, H_DIM, I_DIM, nullptr, (const float*)px2);
}

// round 6
// speedup vs baseline: 4.7662x; 4.7662x over previous
#include <cuda_runtime.h>
#include <cstdint>
#include <cstddef>
#include <math_constants.h>

// ---------------------------------------------------------------------------
// Problem constants (B=1)
// ---------------------------------------------------------------------------
#define S_LEN 2048
#define H_DIM 4096
#define NHEAD 32
#define NKV   8
#define HD    128
#define I_DIM 11008
#define NEGF  (-3.4028234663852886e38f)   // jnp.finfo(float32).min

// ---------------------------------------------------------------------------
// Scratch (static device globals -- no allocation allowed)
// ---------------------------------------------------------------------------
__device__ float g_concat[(size_t)S_LEN * 2 * H_DIM];
__device__ float g_x     [(size_t)S_LEN * H_DIM];
__device__ float g_h     [(size_t)S_LEN * H_DIM];
__device__ float g_q     [(size_t)S_LEN * NHEAD * HD];   // pre-rope
__device__ float g_k     [(size_t)S_LEN * NKV * HD];     // pre-rope
__device__ float g_v     [(size_t)S_LEN * NKV * HD];
__device__ float g_q2    [(size_t)S_LEN * NHEAD * HD];   // post-rope
__device__ float g_k2    [(size_t)S_LEN * NKV * HD];     // post-rope
__device__ float g_cos   [(size_t)S_LEN * HD];
__device__ float g_sin   [(size_t)S_LEN * HD];
__device__ float g_attno [(size_t)S_LEN * NHEAD * HD];
__device__ float g_x2    [(size_t)S_LEN * H_DIM];
__device__ float g_h2    [(size_t)S_LEN * H_DIM];
__device__ float g_gate  [(size_t)S_LEN * I_DIM];
__device__ float g_act   [(size_t)S_LEN * I_DIM];
__device__ float g_scores[(size_t)NHEAD * S_LEN * S_LEN]; // 512MB

// ---------------------------------------------------------------------------
// concat([inputs_embeds, hidden_states]) -> g_concat
// ---------------------------------------------------------------------------
__global__ void concat_kernel(const float* __restrict__ emb,
                              const float* __restrict__ hid)
{
    int t = blockIdx.x * 256 + threadIdx.x;
    int s  = t >> 11;
    int c4 = t & 2047;
    float4 v;
    if (c4 < 1024) v = ((const float4*)emb)[(size_t)s * 1024 + c4];
    else           v = ((const float4*)hid)[(size_t)s * 1024 + (c4 - 1024)];
    ((float4*)g_concat)[t] = v;
}

// ---------------------------------------------------------------------------
// Double-buffered NT SGEMM: C[M,N] = A[M,K] @ B[N,K]^T (+epilogue)
//   EPI 0: none | 1: +bias | 2: +resid | 3: *silu(resid)
// 128x128x16 tiles, 256 threads, 8x8 micro-tile. Same math/epilogues as the
// r5-passing version; only smem pipelining added.
// ---------------------------------------------------------------------------
template <int EPI>
__global__ void __launch_bounds__(256, 2)
sgemm_nt(const float* __restrict__ A, const float* __restrict__ B,
         float* __restrict__ C, int M, int N, int K,
         const float* __restrict__ bias, const float* __restrict__ resid)
{
    __shared__ float As[2][16][132];
    __shared__ float Bs[2][16][132];

    const int tid = threadIdx.x;
    const int tx = tid & 15;
    const int ty = tid >> 4;
    const int lrow = tid >> 2;           // 0..63
    const int lk = (tid & 3) << 2;       // 0,4,8,12

    const float* Ab = A + (size_t)blockIdx.y * 128 * K + (size_t)lrow * K + lk;
    const float* Bb = B + (size_t)blockIdx.x * 128 * K + (size_t)lrow * K + lk;
    const size_t half = (size_t)64 * K;

    float acc[8][8];
#pragma unroll
    for (int i = 0; i < 8; i++)
#pragma unroll
        for (int j = 0; j < 8; j++) acc[i][j] = 0.f;

    // preload k-tile 0 into buffer 0
    {
        float4 a0 = *(const float4*)(Ab);
        float4 a1 = *(const float4*)(Ab + half);
        float4 b0 = *(const float4*)(Bb);
        float4 b1 = *(const float4*)(Bb + half);
        As[0][lk + 0][lrow] = a0.x; As[0][lk + 1][lrow] = a0.y;
        As[0][lk + 2][lrow] = a0.z; As[0][lk + 3][lrow] = a0.w;
        As[0][lk + 0][lrow + 64] = a1.x; As[0][lk + 1][lrow + 64] = a1.y;
        As[0][lk + 2][lrow + 64] = a1.z; As[0][lk + 3][lrow + 64] = a1.w;
        Bs[0][lk + 0][lrow] = b0.x; Bs[0][lk + 1][lrow] = b0.y;
        Bs[0][lk + 2][lrow] = b0.z; Bs[0][lk + 3][lrow] = b0.w;
        Bs[0][lk + 0][lrow + 64] = b1.x; Bs[0][lk + 1][lrow + 64] = b1.y;
        Bs[0][lk + 2][lrow + 64] = b1.z; Bs[0][lk + 3][lrow + 64] = b1.w;
    }
    __syncthreads();

    const int nk = K >> 4;
    for (int kt = 0; kt < nk; kt++) {
        const int cur = kt & 1;
        float4 na0, na1, nb0, nb1;
        const bool more = (kt + 1 < nk);
        if (more) {
            const float* Ap = Ab + (kt + 1) * 16;
            const float* Bp = Bb + (kt + 1) * 16;
            na0 = *(const float4*)(Ap);
            na1 = *(const float4*)(Ap + half);
            nb0 = *(const float4*)(Bp);
            nb1 = *(const float4*)(Bp + half);
        }

#pragma unroll
        for (int kk = 0; kk < 16; kk++) {
            float4 av0 = *(const float4*)&As[cur][kk][ty * 8];
            float4 av1 = *(const float4*)&As[cur][kk][ty * 8 + 4];
            float4 bv0 = *(const float4*)&Bs[cur][kk][tx * 8];
            float4 bv1 = *(const float4*)&Bs[cur][kk][tx * 8 + 4];
            float av[8] = {av0.x, av0.y, av0.z, av0.w, av1.x, av1.y, av1.z, av1.w};
            float bv[8] = {bv0.x, bv0.y, bv0.z, bv0.w, bv1.x, bv1.y, bv1.z, bv1.w};
#pragma unroll
            for (int i = 0; i < 8; i++)
#pragma unroll
                for (int j = 0; j < 8; j++) acc[i][j] += av[i] * bv[j];
        }

        if (more) {
            const int nxt = cur ^ 1;
            As[nxt][lk + 0][lrow] = na0.x; As[nxt][lk + 1][lrow] = na0.y;
            As[nxt][lk + 2][lrow] = na0.z; As[nxt][lk + 3][lrow] = na0.w;
            As[nxt][lk + 0][lrow + 64] = na1.x; As[nxt][lk + 1][lrow + 64] = na1.y;
            As[nxt][lk + 2][lrow + 64] = na1.z; As[nxt][lk + 3][lrow + 64] = na1.w;
            Bs[nxt][lk + 0][lrow] = nb0.x; Bs[nxt][lk + 1][lrow] = nb0.y;
            Bs[nxt][lk + 2][lrow] = nb0.z; Bs[nxt][lk + 3][lrow] = nb0.w;
            Bs[nxt][lk + 0][lrow + 64] = nb1.x; Bs[nxt][lk + 1][lrow + 64] = nb1.y;
            Bs[nxt][lk + 2][lrow + 64] = nb1.z; Bs[nxt][lk + 3][lrow + 64] = nb1.w;
        }
        __syncthreads();
    }

#pragma unroll
    for (int i = 0; i < 8; i++) {
        int row = blockIdx.y * 128 + ty * 8 + i;
#pragma unroll
        for (int j = 0; j < 8; j++) {
            int col = blockIdx.x * 128 + tx * 8 + j;
            float v = acc[i][j];
            if (EPI == 1) v += bias[col];
            if (EPI == 2) v += resid[(size_t)row * N + col];
            if (EPI == 3) {
                float g = resid[(size_t)row * N + col];
                v *= g / (1.f + expf(-g));
            }
            C[(size_t)row * N + col] = v;
        }
    }
}

// ---------------------------------------------------------------------------
// RMSNorm (r5-verified, verbatim)
// ---------------------------------------------------------------------------
__global__ void __launch_bounds__(256)
rmsnorm2_kernel(const float* __restrict__ x, const float* __restrict__ w,
                float* __restrict__ out)
{
    __shared__ float sh[256];
    int row = blockIdx.x;
    const float* xr = x + (size_t)row * H_DIM;
    float acc = 0.f;
    for (int c = threadIdx.x; c < H_DIM; c += 256) {
        float v = xr[c];
        acc += v * v;
    }
    sh[threadIdx.x] = acc;
    __syncthreads();
    for (int s2 = 128; s2 > 0; s2 >>= 1) {
        if (threadIdx.x < s2) sh[threadIdx.x] += sh[threadIdx.x + s2];
        __syncthreads();
    }
    float r = rsqrtf(sh[0] / (float)H_DIM + 1e-6f);
    for (int c = threadIdx.x; c < H_DIM; c += 256)
        out[(size_t)row * H_DIM + c] = xr[c] * r * w[c];
}

// ---------------------------------------------------------------------------
// RoPE stage 1: cos/sin caches (r5-verified, verbatim)
// ---------------------------------------------------------------------------
__global__ void rope_cache_kernel(const int* __restrict__ pos32)
{
    int t = blockIdx.x * 256 + threadIdx.x;     // s*128 + d
    int s = t >> 7;
    int d = t & 127;
    long long pv;
    if (pos32[1] == 1) pv = (long long)pos32[s];
    else               pv = ((const long long*)pos32)[s];
    int j = (d < 64) ? d : d - 64;
    float invf = 1.0f / powf(10000.0f, (float)(2 * j) / 128.0f);
    float ang = (float)pv * invf;
    g_cos[t] = cosf(ang);
    g_sin[t] = sinf(ang);
}

// ---------------------------------------------------------------------------
// RoPE stage 2: out-of-place apply (r5-verified, verbatim)
// ---------------------------------------------------------------------------
__global__ void rope_apply_kernel()
{
    int t = blockIdx.x * 256 + threadIdx.x;     // total 2048*5120
    int s = t / 5120;
    int c = t % 5120;
    const float* cs = g_cos + (size_t)s * HD;
    const float* sn = g_sin + (size_t)s * HD;
    if (c < 4096) {
        int d = c & 127;
        const float* qrow = g_q + (size_t)s * 4096;
        float rh = (d < 64) ? -qrow[c + 64] : qrow[c - 64];
        g_q2[(size_t)s * 4096 + c] = qrow[c] * cs[d] + rh * sn[d];
    } else {
        int cc = c - 4096;
        int d = cc & 127;
        const float* krow = g_k + (size_t)s * 1024;
        float rh = (d < 64) ? -krow[cc + 64] : krow[cc - 64];
        g_k2[(size_t)s * 1024 + cc] = krow[cc] * cs[d] + rh * sn[d];
    }
}

// ---------------------------------------------------------------------------
// Tiled per-head QK^T with the exact r5 score semantics:
// scores[h,q,k] = dot*scale + ((k>q)?NEG:0) + ((amask[k]>0.5)?0:NEG)
// A = g_q2 (row stride 4096, col off h*128); B = g_k2 (stride 1024, off (h>>2)*128)
// Upper-triangle tiles: fill NEG and return (row stays fully defined).
// ---------------------------------------------------------------------------
__global__ void __launch_bounds__(256, 2)
qk_tiled(const float* __restrict__ amask)
{
    const int bx = blockIdx.x;      // k tile
    const int by = blockIdx.y;      // q tile
    const int h  = blockIdx.z;
    const int tid = threadIdx.x;
    float* Crow = g_scores + (size_t)h * S_LEN * S_LEN;

    if (bx > by) {
        for (int i = tid; i < 128 * 128; i += 256) {
            int r = i >> 7, c = i & 127;
            Crow[(size_t)(by * 128 + r) * S_LEN + bx * 128 + c] = NEGF;
        }
        return;
    }

    __shared__ float As[2][16][132];
    __shared__ float Bs[2][16][132];

    const int tx = tid & 15;
    const int ty = tid >> 4;
    const int lrow = tid >> 2;
    const int lk = (tid & 3) << 2;

    const float* Ab = g_q2 + (size_t)(by * 128 + lrow) * 4096 + h * 128 + lk;
    const float* Bb = g_k2 + (size_t)(bx * 128 + lrow) * 1024 + (h >> 2) * 128 + lk;
    const size_t ahalf = (size_t)64 * 4096;
    const size_t bhalf = (size_t)64 * 1024;

    float acc[8][8];
#pragma unroll
    for (int i = 0; i < 8; i++)
#pragma unroll
        for (int j = 0; j < 8; j++) acc[i][j] = 0.f;

    {
        float4 a0 = *(const float4*)(Ab);
        float4 a1 = *(const float4*)(Ab + ahalf);
        float4 b0 = *(const float4*)(Bb);
        float4 b1 = *(const float4*)(Bb + bhalf);
        As[0][lk + 0][lrow] = a0.x; As[0][lk + 1][lrow] = a0.y;
        As[0][lk + 2][lrow] = a0.z; As[0][lk + 3][lrow] = a0.w;
        As[0][lk + 0][lrow + 64] = a1.x; As[0][lk + 1][lrow + 64] = a1.y;
        As[0][lk + 2][lrow + 64] = a1.z; As[0][lk + 3][lrow + 64] = a1.w;
        Bs[0][lk + 0][lrow] = b0.x; Bs[0][lk + 1][lrow] = b0.y;
        Bs[0][lk + 2][lrow] = b0.z; Bs[0][lk + 3][lrow] = b0.w;
        Bs[0][lk + 0][lrow + 64] = b1.x; Bs[0][lk + 1][lrow + 64] = b1.y;
        Bs[0][lk + 2][lrow + 64] = b1.z; Bs[0][lk + 3][lrow + 64] = b1.w;
    }
    __syncthreads();

    const int nk = 128 >> 4;        // 8
    for (int kt = 0; kt < nk; kt++) {
        const int cur = kt & 1;
        float4 na0, na1, nb0, nb1;
        const bool more = (kt + 1 < nk);
        if (more) {
            const float* Ap = Ab + (kt + 1) * 16;
            const float* Bp = Bb + (kt + 1) * 16;
            na0 = *(const float4*)(Ap);
            na1 = *(const float4*)(Ap + ahalf);
            nb0 = *(const float4*)(Bp);
            nb1 = *(const float4*)(Bp + bhalf);
        }

#pragma unroll
        for (int kk = 0; kk < 16; kk++) {
            float4 av0 = *(const float4*)&As[cur][kk][ty * 8];
            float4 av1 = *(const float4*)&As[cur][kk][ty * 8 + 4];
            float4 bv0 = *(const float4*)&Bs[cur][kk][tx * 8];
            float4 bv1 = *(const float4*)&Bs[cur][kk][tx * 8 + 4];
            float av[8] = {av0.x, av0.y, av0.z, av0.w, av1.x, av1.y, av1.z, av1.w};
            float bv[8] = {bv0.x, bv0.y, bv0.z, bv0.w, bv1.x, bv1.y, bv1.z, bv1.w};
#pragma unroll
            for (int i = 0; i < 8; i++)
#pragma unroll
                for (int j = 0; j < 8; j++) acc[i][j] += av[i] * bv[j];
        }

        if (more) {
            const int nxt = cur ^ 1;
            As[nxt][lk + 0][lrow] = na0.x; As[nxt][lk + 1][lrow] = na0.y;
            As[nxt][lk + 2][lrow] = na0.z; As[nxt][lk + 3][lrow] = na0.w;
            As[nxt][lk + 0][lrow + 64] = na1.x; As[nxt][lk + 1][lrow + 64] = na1.y;
            As[nxt][lk + 2][lrow + 64] = na1.z; As[nxt][lk + 3][lrow + 64] = na1.w;
            Bs[nxt][lk + 0][lrow] = nb0.x; Bs[nxt][lk + 1][lrow] = nb0.y;
            Bs[nxt][lk + 2][lrow] = nb0.z; Bs[nxt][lk + 3][lrow] = nb0.w;
            Bs[nxt][lk + 0][lrow + 64] = nb1.x; Bs[nxt][lk + 1][lrow + 64] = nb1.y;
            Bs[nxt][lk + 2][lrow + 64] = nb1.z; Bs[nxt][lk + 3][lrow + 64] = nb1.w;
        }
        __syncthreads();
    }

    const float scale = 0.08838834764831845f;
#pragma unroll
    for (int i = 0; i < 8; i++) {
        int qq = by * 128 + ty * 8 + i;
#pragma unroll
        for (int j = 0; j < 8; j++) {
            int kk = bx * 128 + tx * 8 + j;
            float m = ((kk > qq) ? NEGF : 0.f) + ((amask[kk] > 0.5f) ? 0.f : NEGF);
            Crow[(size_t)qq * S_LEN + kk] = acc[i][j] * scale + m;
        }
    }
}

// ---------------------------------------------------------------------------
// Softmax: warp per (h,q) row, exact two-pass (r5-verified, verbatim)
// ---------------------------------------------------------------------------
__global__ void __launch_bounds__(256)
softmax2_kernel()
{
    int gw = (blockIdx.x * 256 + threadIdx.x) >> 5;   // h*2048 + q
    int lane = threadIdx.x & 31;
    float* row = g_scores + (size_t)gw * 2048;

    float m = -CUDART_INF_F;
    for (int k = lane; k < 2048; k += 32) m = fmaxf(m, row[k]);
#pragma unroll
    for (int o = 16; o; o >>= 1) m = fmaxf(m, __shfl_xor_sync(0xffffffffu, m, o));

    float sum = 0.f;
    for (int k = lane; k < 2048; k += 32) {
        float p = expf(row[k] - m);
        row[k] = p;
        sum += p;
    }
#pragma unroll
    for (int o = 16; o; o >>= 1) sum += __shfl_xor_sync(0xffffffffu, sum, o);
    float inv = 1.f / sum;
    for (int k = lane; k < 2048; k += 32) row[k] *= inv;
}

// ---------------------------------------------------------------------------
// P @ V per head (NN GEMM) — r3 pv_gemm, exonerated by pv_gemm==pv_naive.
// k-tiles only up to diagonal; P beyond q is exactly 0 after softmax.
// ---------------------------------------------------------------------------
__global__ void __launch_bounds__(256, 2)
pv_gemm()
{
    const int by = blockIdx.x;      // q tile
    const int h  = blockIdx.y;

    __shared__ float Ps[16][132];   // Ps[k][q]
    __shared__ float Vs[16][132];   // Vs[k][d]

    const int tid = threadIdx.x;
    const int tx = tid & 15;
    const int ty = tid >> 4;
    const int lrow = tid >> 2;
    const int lk = (tid & 3) << 2;

    const float* Pb = g_scores + ((size_t)h * S_LEN + by * 128) * S_LEN;
    const float* Vb = g_v + (h >> 2) * HD;

    float acc[8][8];
#pragma unroll
    for (int i = 0; i < 8; i++)
#pragma unroll
        for (int j = 0; j < 8; j++) acc[i][j] = 0.f;

    const int kend = (by + 1) * 128;
    for (int k0 = 0; k0 < kend; k0 += 16) {
        float4 p0 = *(const float4*)(Pb + (size_t)lrow * S_LEN + k0 + lk);
        float4 p1 = *(const float4*)(Pb + (size_t)(lrow + 64) * S_LEN + k0 + lk);
        Ps[lk + 0][lrow] = p0.x; Ps[lk + 1][lrow] = p0.y;
        Ps[lk + 2][lrow] = p0.z; Ps[lk + 3][lrow] = p0.w;
        Ps[lk + 0][lrow + 64] = p1.x; Ps[lk + 1][lrow + 64] = p1.y;
        Ps[lk + 2][lrow + 64] = p1.z; Ps[lk + 3][lrow + 64] = p1.w;
#pragma unroll
        for (int t = 0; t < 2; t++) {
            int j = tid + t * 256;
            int vr = j >> 5;
            int vc = (j & 31) * 4;
            float4 vv = *(const float4*)(Vb + (size_t)(k0 + vr) * (NKV * HD) + vc);
            Vs[vr][vc + 0] = vv.x; Vs[vr][vc + 1] = vv.y;
            Vs[vr][vc + 2] = vv.z; Vs[vr][vc + 3] = vv.w;
        }
        __syncthreads();

#pragma unroll
        for (int kk = 0; kk < 16; kk++) {
            float4 av0 = *(const float4*)&Ps[kk][ty * 8];
            float4 av1 = *(const float4*)&Ps[kk][ty * 8 + 4];
            float4 bv0 = *(const float4*)&Vs[kk][tx * 8];
            float4 bv1 = *(const float4*)&Vs[kk][tx * 8 + 4];
            float av[8] = {av0.x, av0.y, av0.z, av0.w, av1.x, av1.y, av1.z, av1.w};
            float bv[8] = {bv0.x, bv0.y, bv0.z, bv0.w, bv1.x, bv1.y, bv1.z, bv1.w};
#pragma unroll
            for (int i = 0; i < 8; i++)
#pragma unroll
                for (int j = 0; j < 8; j++) acc[i][j] += av[i] * bv[j];
        }
        __syncthreads();
    }

#pragma unroll
    for (int i = 0; i < 8; i++) {
        int row = by * 128 + ty * 8 + i;
#pragma unroll
        for (int j = 0; j < 8; j++) {
            g_attno[(size_t)row * (NHEAD * HD) + h * HD + tx * 8 + j] = acc[i][j];
        }
    }
}

// ---------------------------------------------------------------------------
// kernel_launch
// ---------------------------------------------------------------------------
extern "C" void kernel_launch(void* const* d_in, const int* in_sizes, int n_in,
                              void* d_out, int out_size)
{
    const float* hidden      = (const float*)d_in[0];
    const float* embeds      = (const float*)d_in[1];
    const float* amask       = (const float*)d_in[2];
    const float* fc_w        = (const float*)d_in[3];
    const float* fc_b        = (const float*)d_in[4];
    const float* in_norm_w   = (const float*)d_in[5];
    const float* q_w         = (const float*)d_in[6];
    const float* k_w         = (const float*)d_in[7];
    const float* v_w         = (const float*)d_in[8];
    const float* o_w         = (const float*)d_in[9];
    const float* post_norm_w = (const float*)d_in[10];
    const float* gate_w      = (const float*)d_in[11];
    const float* up_w        = (const float*)d_in[12];
    const float* down_w      = (const float*)d_in[13];
    const int* pos           = (const int*)d_in[14];
    float* out = (float*)d_out;

    void *pcat, *px, *ph, *pq, *pk, *pv, *pattn, *px2, *ph2, *pgate, *pact;
    cudaGetSymbolAddress(&pcat, g_concat);
    cudaGetSymbolAddress(&px, g_x);
    cudaGetSymbolAddress(&ph, g_h);
    cudaGetSymbolAddress(&pq, g_q);
    cudaGetSymbolAddress(&pk, g_k);
    cudaGetSymbolAddress(&pv, g_v);
    cudaGetSymbolAddress(&pattn, g_attno);
    cudaGetSymbolAddress(&px2, g_x2);
    cudaGetSymbolAddress(&ph2, g_h2);
    cudaGetSymbolAddress(&pgate, g_gate);
    cudaGetSymbolAddress(&pact, g_act);

    // 1. concat
    concat_kernel<<<(S_LEN * 2048) / 256, 256>>>(embeds, hidden);

    // 2. fc
    sgemm_nt<1><<<dim3(H_DIM / 128, S_LEN / 128), 256>>>(
        (const float*)pcat, fc_w, (float*)px, S_LEN, H_DIM, 2 * H_DIM, fc_b, nullptr);

    // 3. rmsnorm1
    rmsnorm2_kernel<<<S_LEN, 256>>>((const float*)px, in_norm_w, (float*)ph);

    // 4. q/k/v projections (tiled)
    sgemm_nt<0><<<dim3(4096 / 128, S_LEN / 128), 256>>>(
        (const float*)ph, q_w, (float*)pq, S_LEN, 4096, 4096, nullptr, nullptr);
    sgemm_nt<0><<<dim3(1024 / 128, S_LEN / 128), 256>>>(
        (const float*)ph, k_w, (float*)pk, S_LEN, 1024, 4096, nullptr, nullptr);
    sgemm_nt<0><<<dim3(1024 / 128, S_LEN / 128), 256>>>(
        (const float*)ph, v_w, (float*)pv, S_LEN, 1024, 4096, nullptr, nullptr);

    // 5. RoPE
    rope_cache_kernel<<<(S_LEN * HD) / 256, 256>>>(pos);
    rope_apply_kernel<<<(S_LEN * 5120) / 256, 256>>>();

    // 6. attention: tiled QK^T -> softmax -> tiled PV
    qk_tiled<<<dim3(S_LEN / 128, S_LEN / 128, NHEAD), 256>>>(amask);
    softmax2_kernel<<<(NHEAD * S_LEN * 32) / 256, 256>>>();
    pv_gemm<<<dim3(S_LEN / 128, NHEAD), 256>>>();

    // 7. o-proj + residual (tiled)
    sgemm_nt<2><<<dim3(4096 / 128, S_LEN / 128), 256>>>(
        (const float*)pattn, o_w, (float*)px2, S_LEN, 4096, 4096, nullptr, (const float*)px);

    // 8. rmsnorm2
    rmsnorm2_kernel<<<S_LEN, 256>>>((const float*)px2, post_norm_w, (float*)ph2);

    // 9-11. MLP
    sgemm_nt<0><<<dim3(I_DIM / 128, S_LEN / 128), 256>>>(
        (const float*)ph2, gate_w, (float*)pgate, S_LEN, I_DIM, 4096, nullptr, nullptr);
    sgemm_nt<3><<<dim3(I_DIM / 128, S_LEN / 128), 256>>>(
        (const float*)ph2, up_w, (float*)pact, S_LEN, I_DIM, 4096, nullptr, (const float*)pgate);
    sgemm_nt<2><<<dim3(H_DIM / 128, S_LEN / 128), 256>>>(
        (const float*)pact, down_w, out, S_LEN, H_DIM, I_DIM, nullptr, (const float*)px2);
}

// round 10
// speedup vs baseline: 10.4106x; 2.1843x over previous
#include <cuda_runtime.h>
#include <cuda_bf16.h>
#include <cstdint>
#include <cstddef>
#include <math_constants.h>

// ---------------------------------------------------------------------------
// Problem constants (B=1)
// ---------------------------------------------------------------------------
#define S_LEN 2048
#define H_DIM 4096
#define NHEAD 32
#define NKV   8
#define HD    128
#define I_DIM 11008
#define NEGF  (-3.4028234663852886e38f)   // jnp.finfo(float32).min

// ---------------------------------------------------------------------------
// fp32 scratch
// ---------------------------------------------------------------------------
__device__ float g_x     [(size_t)S_LEN * H_DIM];
__device__ float g_h     [(size_t)S_LEN * H_DIM];
__device__ float g_q     [(size_t)S_LEN * NHEAD * HD];
__device__ float g_k     [(size_t)S_LEN * NKV * HD];
__device__ float g_v     [(size_t)S_LEN * NKV * HD];
__device__ float g_q2    [(size_t)S_LEN * NHEAD * HD];
__device__ float g_k2    [(size_t)S_LEN * NKV * HD];
__device__ float g_cos   [(size_t)S_LEN * HD];
__device__ float g_sin   [(size_t)S_LEN * HD];
__device__ float g_attno [(size_t)S_LEN * NHEAD * HD];
__device__ float g_x2    [(size_t)S_LEN * H_DIM];
__device__ float g_h2    [(size_t)S_LEN * H_DIM];
__device__ float g_gate  [(size_t)S_LEN * I_DIM];
__device__ float g_act   [(size_t)S_LEN * I_DIM];
__device__ float g_scores[(size_t)NHEAD * S_LEN * S_LEN];

// ---------------------------------------------------------------------------
// bf16 split scratch (hi/lo), 16B-aligned for cp.async
// ---------------------------------------------------------------------------
#define BF16BUF(name, count) \
    __device__ __align__(16) __nv_bfloat16 name##_h[count]; \
    __device__ __align__(16) __nv_bfloat16 name##_l[count];

BF16BUF(g_cat,   (size_t)S_LEN * 2 * H_DIM)
BF16BUF(g_hb,    (size_t)S_LEN * H_DIM)
BF16BUF(g_atb,   (size_t)S_LEN * NHEAD * HD)
BF16BUF(g_h2b,   (size_t)S_LEN * H_DIM)
BF16BUF(g_actb,  (size_t)S_LEN * I_DIM)
BF16BUF(g_fcw,   (size_t)H_DIM * 2 * H_DIM)
BF16BUF(g_qw,    (size_t)H_DIM * H_DIM)
BF16BUF(g_kw,    (size_t)NKV * HD * H_DIM)
BF16BUF(g_vw,    (size_t)NKV * HD * H_DIM)
BF16BUF(g_ow,    (size_t)H_DIM * H_DIM)
BF16BUF(g_gw,    (size_t)I_DIM * H_DIM)
BF16BUF(g_uw,    (size_t)I_DIM * H_DIM)
BF16BUF(g_dw,    (size_t)H_DIM * I_DIM)

// ---------------------------------------------------------------------------
// PTX helpers (base-target only: cp.async / ldmatrix / mma.sync — no tcgen05)
// ---------------------------------------------------------------------------
__device__ __forceinline__ uint32_t smem_to_u32(const void* p) {
    uint32_t a;
    asm("{ .reg .u64 t; cvta.to.shared.u64 t, %1; cvt.u32.u64 %0, t; }"
        : "=r"(a) : "l"(p));
    return a;
}
#define CP16(dst_u32, src_ptr) \
    asm volatile("cp.async.cg.shared.global [%0], [%1], 16;" \
                 :: "r"(dst_u32), "l"(src_ptr) : "memory")
#define CP_COMMIT() asm volatile("cp.async.commit_group;" ::: "memory")
#define CP_WAIT1()  asm volatile("cp.async.wait_group 1;" ::: "memory")

#define LDSM4(r, addr) \
    asm volatile("ldmatrix.sync.aligned.m8n8.x4.shared.b16 {%0,%1,%2,%3}, [%4];" \
        : "=r"((r)[0]), "=r"((r)[1]), "=r"((r)[2]), "=r"((r)[3]) : "r"(addr))

#define MMA_BF16(d, a, b) \
    asm volatile("mma.sync.aligned.m16n8k16.row.col.f32.bf16.bf16.f32 " \
        "{%0,%1,%2,%3}, {%4,%5,%6,%7}, {%8,%9}, {%0,%1,%2,%3};" \
        : "+f"((d)[0]), "+f"((d)[1]), "+f"((d)[2]), "+f"((d)[3]) \
        : "r"((a)[0]), "r"((a)[1]), "r"((a)[2]), "r"((a)[3]), \
          "r"((b)[0]), "r"((b)[1]))

// Swizzled byte offset within one 128-row x 32-col bf16 tile (64B rows).
// Key spreads ldmatrix's 8-row reads across distinct 16B bank groups.
__device__ __forceinline__ uint32_t sw_off(int row, int c16) {
    int key = (row & 3) ^ ((row >> 2) & 1);
    return (uint32_t)(row * 64 + ((c16 ^ key) << 4));
}

// ---------------------------------------------------------------------------
// Split-bf16 NT GEMM on tensor cores (mma.sync):
//   C[M,N] = (Ah+Al)[M,K] @ (Bh+Bl)[N,K]^T  (+epilogue)
// 128x128 CTA tile, K-chunk 32, double-buffered cp.async, 256 threads.
// Warp tile 64x32. 3 products: AhBh + AhBl + AlBh (fp32 accum).
//   EPI 0: none | 1: +bias[col] | 2: +resid | 3: *silu(resid)
// ---------------------------------------------------------------------------
#define TG_STAGE 32768
#define TG_SMEM  (2 * TG_STAGE)

template <int EPI>
__global__ void __launch_bounds__(256, 1)
tgemm(const __nv_bfloat16* __restrict__ Ah, const __nv_bfloat16* __restrict__ Al,
      const __nv_bfloat16* __restrict__ Bh, const __nv_bfloat16* __restrict__ Bl,
      float* __restrict__ C, int M, int N, int K,
      const float* __restrict__ bias, const float* __restrict__ resid)
{
    extern __shared__ char smem[];
    const uint32_t sbase = smem_to_u32(smem);
    const int tid = threadIdx.x;
    const int wid = tid >> 5;
    const int lane = tid & 31;
    const int bx = blockIdx.x;      // N tile
    const int by = blockIdx.y;      // M tile

    const int wm = (wid & 1) * 64;  // warp row offset within 128 tile
    const int wn = (wid >> 1) * 32; // warp col offset

    const __nv_bfloat16* Ahb = Ah + (size_t)by * 128 * K;
    const __nv_bfloat16* Alb = Al + (size_t)by * 128 * K;
    const __nv_bfloat16* Bhb = Bh + (size_t)bx * 128 * K;
    const __nv_bfloat16* Blb = Bl + (size_t)bx * 128 * K;

    float acc[4][4][4];
#pragma unroll
    for (int mi = 0; mi < 4; mi++)
#pragma unroll
        for (int ni = 0; ni < 4; ni++)
#pragma unroll
            for (int r = 0; r < 4; r++) acc[mi][ni][r] = 0.f;

    // region offsets inside one stage: Ah:0  Al:8K  Bh:16K  Bl:24K
    auto load_chunk = [&](int ch, int buf) {
        const uint32_t sb = sbase + buf * TG_STAGE;
        const size_t kof = (size_t)ch * 32;
#pragma unroll
        for (int j = 0; j < 2; j++) {
            int cidx = tid + j * 256;           // 0..511
            int row = cidx >> 2;
            int c16 = cidx & 3;
            uint32_t so = sw_off(row, c16);
            size_t go = (size_t)row * K + kof + c16 * 8;
            CP16(sb + so,         Ahb + go);
            CP16(sb + 8192 + so,  Alb + go);
            CP16(sb + 16384 + so, Bhb + go);
            CP16(sb + 24576 + so, Blb + go);
        }
        CP_COMMIT();
    };

    const int nch = K >> 5;
    load_chunk(0, 0);

    for (int i = 0; i < nch; i++) {
        const int b = i & 1;
        if (i + 1 < nch) load_chunk(i + 1, b ^ 1);
        else CP_COMMIT();           // empty group keeps wait_group 1 semantics
        CP_WAIT1();                 // chunk i resident
        __syncthreads();

        const uint32_t sb = sbase + b * TG_STAGE;
        const uint32_t sAh = sb, sAl = sb + 8192, sBh = sb + 16384, sBl = sb + 24576;

#pragma unroll
        for (int ks = 0; ks < 2; ks++) {
            uint32_t ah[4][4], al[4][4], bh[2][4], bl[2][4];
            const int c16 = ks * 2 + (lane >> 4);
#pragma unroll
            for (int mi = 0; mi < 4; mi++) {
                int row = wm + mi * 16 + (lane & 15);
                uint32_t off = sw_off(row, c16);
                LDSM4(ah[mi], sAh + off);
                LDSM4(al[mi], sAl + off);
            }
#pragma unroll
            for (int pi = 0; pi < 2; pi++) {
                int row = wn + pi * 16 + (lane & 15);
                uint32_t off = sw_off(row, c16);
                LDSM4(bh[pi], sBh + off);
                LDSM4(bl[pi], sBl + off);
            }
#pragma unroll
            for (int mi = 0; mi < 4; mi++) {
#pragma unroll
                for (int ni = 0; ni < 4; ni++) {
                    const int pi = ni >> 1, s = ni & 1;
                    uint32_t bfh[2] = {bh[pi][s], bh[pi][2 + s]};
                    uint32_t bfl[2] = {bl[pi][s], bl[pi][2 + s]};
                    MMA_BF16(acc[mi][ni], ah[mi], bfh);
                    MMA_BF16(acc[mi][ni], ah[mi], bfl);
                    MMA_BF16(acc[mi][ni], al[mi], bfh);
                }
            }
        }
        __syncthreads();            // protect buffer b before next overwrite
    }

    // epilogue: mma C layout -> rows g, g+8; cols tg*2, tg*2+1
    const int g = lane >> 2;
    const int tg = (lane & 3) * 2;
    auto emit = [&](int row, int col, float v) {
        if (EPI == 1) v += bias[col];
        if (EPI == 2) v += resid[(size_t)row * N + col];
        if (EPI == 3) {
            float gg = resid[(size_t)row * N + col];
            v *= gg / (1.f + expf(-gg));
        }
        C[(size_t)row * N + col] = v;
    };
#pragma unroll
    for (int mi = 0; mi < 4; mi++) {
#pragma unroll
        for (int ni = 0; ni < 4; ni++) {
            int r0 = by * 128 + wm + mi * 16 + g;
            int c0 = bx * 128 + wn + ni * 8 + tg;
            emit(r0,     c0,     acc[mi][ni][0]);
            emit(r0,     c0 + 1, acc[mi][ni][1]);
            emit(r0 + 8, c0,     acc[mi][ni][2]);
            emit(r0 + 8, c0 + 1, acc[mi][ni][3]);
        }
    }
}

// ---------------------------------------------------------------------------
// fp32 -> (hi, lo) bf16 split
// ---------------------------------------------------------------------------
__global__ void split_kernel(const float* __restrict__ src,
                             __nv_bfloat16* __restrict__ hi,
                             __nv_bfloat16* __restrict__ lo)
{
    size_t t = (size_t)blockIdx.x * 256 + threadIdx.x;
    float4 v = ((const float4*)src)[t];
    __nv_bfloat16 hx = __float2bfloat16(v.x);
    __nv_bfloat16 hy = __float2bfloat16(v.y);
    __nv_bfloat16 hz = __float2bfloat16(v.z);
    __nv_bfloat16 hw = __float2bfloat16(v.w);
    __nv_bfloat162 h0; h0.x = hx; h0.y = hy;
    __nv_bfloat162 h1; h1.x = hz; h1.y = hw;
    __nv_bfloat162 l0, l1;
    l0.x = __float2bfloat16(v.x - __bfloat162float(hx));
    l0.y = __float2bfloat16(v.y - __bfloat162float(hy));
    l1.x = __float2bfloat16(v.z - __bfloat162float(hz));
    l1.y = __float2bfloat16(v.w - __bfloat162float(hw));
    ((__nv_bfloat162*)hi)[t * 2 + 0] = h0;
    ((__nv_bfloat162*)hi)[t * 2 + 1] = h1;
    ((__nv_bfloat162*)lo)[t * 2 + 0] = l0;
    ((__nv_bfloat162*)lo)[t * 2 + 1] = l1;
}

// concat([emb, hid]) split directly to bf16 hi/lo
__global__ void concat_split_kernel(const float* __restrict__ emb,
                                    const float* __restrict__ hid)
{
    size_t t = (size_t)blockIdx.x * 256 + threadIdx.x;   // float4 idx over [2048, 8192]
    int s = (int)(t >> 11);
    int c4 = (int)(t & 2047);
    float4 v;
    if (c4 < 1024) v = ((const float4*)emb)[(size_t)s * 1024 + c4];
    else           v = ((const float4*)hid)[(size_t)s * 1024 + (c4 - 1024)];
    __nv_bfloat16 hx = __float2bfloat16(v.x);
    __nv_bfloat16 hy = __float2bfloat16(v.y);
    __nv_bfloat16 hz = __float2bfloat16(v.z);
    __nv_bfloat16 hw = __float2bfloat16(v.w);
    __nv_bfloat162 h0; h0.x = hx; h0.y = hy;
    __nv_bfloat162 h1; h1.x = hz; h1.y = hw;
    __nv_bfloat162 l0, l1;
    l0.x = __float2bfloat16(v.x - __bfloat162float(hx));
    l0.y = __float2bfloat16(v.y - __bfloat162float(hy));
    l1.x = __float2bfloat16(v.z - __bfloat162float(hz));
    l1.y = __float2bfloat16(v.w - __bfloat162float(hw));
    ((__nv_bfloat162*)g_cat_h)[t * 2 + 0] = h0;
    ((__nv_bfloat162*)g_cat_h)[t * 2 + 1] = h1;
    ((__nv_bfloat162*)g_cat_l)[t * 2 + 0] = l0;
    ((__nv_bfloat162*)g_cat_l)[t * 2 + 1] = l1;
}

// ---------------------------------------------------------------------------
// RMSNorm (r5-verified, verbatim)
// ---------------------------------------------------------------------------
__global__ void __launch_bounds__(256)
rmsnorm2_kernel(const float* __restrict__ x, const float* __restrict__ w,
                float* __restrict__ out)
{
    __shared__ float sh[256];
    int row = blockIdx.x;
    const float* xr = x + (size_t)row * H_DIM;
    float acc = 0.f;
    for (int c = threadIdx.x; c < H_DIM; c += 256) {
        float v = xr[c];
        acc += v * v;
    }
    sh[threadIdx.x] = acc;
    __syncthreads();
    for (int s2 = 128; s2 > 0; s2 >>= 1) {
        if (threadIdx.x < s2) sh[threadIdx.x] += sh[threadIdx.x + s2];
        __syncthreads();
    }
    float r = rsqrtf(sh[0] / (float)H_DIM + 1e-6f);
    for (int c = threadIdx.x; c < H_DIM; c += 256)
        out[(size_t)row * H_DIM + c] = xr[c] * r * w[c];
}

// ---------------------------------------------------------------------------
// RoPE (r5-verified, verbatim)
// ---------------------------------------------------------------------------
__global__ void rope_cache_kernel(const int* __restrict__ pos32)
{
    int t = blockIdx.x * 256 + threadIdx.x;
    int s = t >> 7;
    int d = t & 127;
    long long pv;
    if (pos32[1] == 1) pv = (long long)pos32[s];
    else               pv = ((const long long*)pos32)[s];
    int j = (d < 64) ? d : d - 64;
    float invf = 1.0f / powf(10000.0f, (float)(2 * j) / 128.0f);
    float ang = (float)pv * invf;
    g_cos[t] = cosf(ang);
    g_sin[t] = sinf(ang);
}

__global__ void rope_apply_kernel()
{
    int t = blockIdx.x * 256 + threadIdx.x;
    int s = t / 5120;
    int c = t % 5120;
    const float* cs = g_cos + (size_t)s * HD;
    const float* sn = g_sin + (size_t)s * HD;
    if (c < 4096) {
        int d = c & 127;
        const float* qrow = g_q + (size_t)s * 4096;
        float rh = (d < 64) ? -qrow[c + 64] : qrow[c - 64];
        g_q2[(size_t)s * 4096 + c] = qrow[c] * cs[d] + rh * sn[d];
    } else {
        int cc = c - 4096;
        int d = cc & 127;
        const float* krow = g_k + (size_t)s * 1024;
        float rh = (d < 64) ? -krow[cc + 64] : krow[cc - 64];
        g_k2[(size_t)s * 1024 + cc] = krow[cc] * cs[d] + rh * sn[d];
    }
}

// ---------------------------------------------------------------------------
// Tiled per-head QK^T (r6-verified, verbatim)
// ---------------------------------------------------------------------------
__global__ void __launch_bounds__(256, 2)
qk_tiled(const float* __restrict__ amask)
{
    const int bx = blockIdx.x;
    const int by = blockIdx.y;
    const int h  = blockIdx.z;
    const int tid = threadIdx.x;
    float* Crow = g_scores + (size_t)h * S_LEN * S_LEN;

    if (bx > by) {
        for (int i = tid; i < 128 * 128; i += 256) {
            int r = i >> 7, c = i & 127;
            Crow[(size_t)(by * 128 + r) * S_LEN + bx * 128 + c] = NEGF;
        }
        return;
    }

    __shared__ float As[2][16][132];
    __shared__ float Bs[2][16][132];

    const int tx = tid & 15;
    const int ty = tid >> 4;
    const int lrow = tid >> 2;
    const int lk = (tid & 3) << 2;

    const float* Ab = g_q2 + (size_t)(by * 128 + lrow) * 4096 + h * 128 + lk;
    const float* Bb = g_k2 + (size_t)(bx * 128 + lrow) * 1024 + (h >> 2) * 128 + lk;
    const size_t ahalf = (size_t)64 * 4096;
    const size_t bhalf = (size_t)64 * 1024;

    float acc[8][8];
#pragma unroll
    for (int i = 0; i < 8; i++)
#pragma unroll
        for (int j = 0; j < 8; j++) acc[i][j] = 0.f;

    {
        float4 a0 = *(const float4*)(Ab);
        float4 a1 = *(const float4*)(Ab + ahalf);
        float4 b0 = *(const float4*)(Bb);
        float4 b1 = *(const float4*)(Bb + bhalf);
        As[0][lk + 0][lrow] = a0.x; As[0][lk + 1][lrow] = a0.y;
        As[0][lk + 2][lrow] = a0.z; As[0][lk + 3][lrow] = a0.w;
        As[0][lk + 0][lrow + 64] = a1.x; As[0][lk + 1][lrow + 64] = a1.y;
        As[0][lk + 2][lrow + 64] = a1.z; As[0][lk + 3][lrow + 64] = a1.w;
        Bs[0][lk + 0][lrow] = b0.x; Bs[0][lk + 1][lrow] = b0.y;
        Bs[0][lk + 2][lrow] = b0.z; Bs[0][lk + 3][lrow] = b0.w;
        Bs[0][lk + 0][lrow + 64] = b1.x; Bs[0][lk + 1][lrow + 64] = b1.y;
        Bs[0][lk + 2][lrow + 64] = b1.z; Bs[0][lk + 3][lrow + 64] = b1.w;
    }
    __syncthreads();

    const int nk = 8;
    for (int kt = 0; kt < nk; kt++) {
        const int cur = kt & 1;
        float4 na0, na1, nb0, nb1;
        const bool more = (kt + 1 < nk);
        if (more) {
            const float* Ap = Ab + (kt + 1) * 16;
            const float* Bp = Bb + (kt + 1) * 16;
            na0 = *(const float4*)(Ap);
            na1 = *(const float4*)(Ap + ahalf);
            nb0 = *(const float4*)(Bp);
            nb1 = *(const float4*)(Bp + bhalf);
        }

#pragma unroll
        for (int kk = 0; kk < 16; kk++) {
            float4 av0 = *(const float4*)&As[cur][kk][ty * 8];
            float4 av1 = *(const float4*)&As[cur][kk][ty * 8 + 4];
            float4 bv0 = *(const float4*)&Bs[cur][kk][tx * 8];
            float4 bv1 = *(const float4*)&Bs[cur][kk][tx * 8 + 4];
            float av[8] = {av0.x, av0.y, av0.z, av0.w, av1.x, av1.y, av1.z, av1.w};
            float bv[8] = {bv0.x, bv0.y, bv0.z, bv0.w, bv1.x, bv1.y, bv1.z, bv1.w};
#pragma unroll
            for (int i = 0; i < 8; i++)
#pragma unroll
                for (int j = 0; j < 8; j++) acc[i][j] += av[i] * bv[j];
        }

        if (more) {
            const int nxt = cur ^ 1;
            As[nxt][lk + 0][lrow] = na0.x; As[nxt][lk + 1][lrow] = na0.y;
            As[nxt][lk + 2][lrow] = na0.z; As[nxt][lk + 3][lrow] = na0.w;
            As[nxt][lk + 0][lrow + 64] = na1.x; As[nxt][lk + 1][lrow + 64] = na1.y;
            As[nxt][lk + 2][lrow + 64] = na1.z; As[nxt][lk + 3][lrow + 64] = na1.w;
            Bs[nxt][lk + 0][lrow] = nb0.x; Bs[nxt][lk + 1][lrow] = nb0.y;
            Bs[nxt][lk + 2][lrow] = nb0.z; Bs[nxt][lk + 3][lrow] = nb0.w;
            Bs[nxt][lk + 0][lrow + 64] = nb1.x; Bs[nxt][lk + 1][lrow + 64] = nb1.y;
            Bs[nxt][lk + 2][lrow + 64] = nb1.z; Bs[nxt][lk + 3][lrow + 64] = nb1.w;
        }
        __syncthreads();
    }

    const float scale = 0.08838834764831845f;
#pragma unroll
    for (int i = 0; i < 8; i++) {
        int qq = by * 128 + ty * 8 + i;
#pragma unroll
        for (int j = 0; j < 8; j++) {
            int kk = bx * 128 + tx * 8 + j;
            float m = ((kk > qq) ? NEGF : 0.f) + ((amask[kk] > 0.5f) ? 0.f : NEGF);
            Crow[(size_t)qq * S_LEN + kk] = acc[i][j] * scale + m;
        }
    }
}

// ---------------------------------------------------------------------------
// Softmax (r5-verified, verbatim)
// ---------------------------------------------------------------------------
__global__ void __launch_bounds__(256)
softmax2_kernel()
{
    int gw = (blockIdx.x * 256 + threadIdx.x) >> 5;
    int lane = threadIdx.x & 31;
    float* row = g_scores + (size_t)gw * 2048;

    float m = -CUDART_INF_F;
    for (int k = lane; k < 2048; k += 32) m = fmaxf(m, row[k]);
#pragma unroll
    for (int o = 16; o; o >>= 1) m = fmaxf(m, __shfl_xor_sync(0xffffffffu, m, o));

    float sum = 0.f;
    for (int k = lane; k < 2048; k += 32) {
        float p = expf(row[k] - m);
        row[k] = p;
        sum += p;
    }
#pragma unroll
    for (int o = 16; o; o >>= 1) sum += __shfl_xor_sync(0xffffffffu, sum, o);
    float inv = 1.f / sum;
    for (int k = lane; k < 2048; k += 32) row[k] *= inv;
}

// ---------------------------------------------------------------------------
// P @ V per head (r6-verified, verbatim)
// ---------------------------------------------------------------------------
__global__ void __launch_bounds__(256, 2)
pv_gemm()
{
    const int by = blockIdx.x;
    const int h  = blockIdx.y;

    __shared__ float Ps[16][132];
    __shared__ float Vs[16][132];

    const int tid = threadIdx.x;
    const int tx = tid & 15;
    const int ty = tid >> 4;
    const int lrow = tid >> 2;
    const int lk = (tid & 3) << 2;

    const float* Pb = g_scores + ((size_t)h * S_LEN + by * 128) * S_LEN;
    const float* Vb = g_v + (h >> 2) * HD;

    float acc[8][8];
#pragma unroll
    for (int i = 0; i < 8; i++)
#pragma unroll
        for (int j = 0; j < 8; j++) acc[i][j] = 0.f;

    const int kend = (by + 1) * 128;
    for (int k0 = 0; k0 < kend; k0 += 16) {
        float4 p0 = *(const float4*)(Pb + (size_t)lrow * S_LEN + k0 + lk);
        float4 p1 = *(const float4*)(Pb + (size_t)(lrow + 64) * S_LEN + k0 + lk);
        Ps[lk + 0][lrow] = p0.x; Ps[lk + 1][lrow] = p0.y;
        Ps[lk + 2][lrow] = p0.z; Ps[lk + 3][lrow] = p0.w;
        Ps[lk + 0][lrow + 64] = p1.x; Ps[lk + 1][lrow + 64] = p1.y;
        Ps[lk + 2][lrow + 64] = p1.z; Ps[lk + 3][lrow + 64] = p1.w;
#pragma unroll
        for (int t = 0; t < 2; t++) {
            int j = tid + t * 256;
            int vr = j >> 5;
            int vc = (j & 31) * 4;
            float4 vv = *(const float4*)(Vb + (size_t)(k0 + vr) * (NKV * HD) + vc);
            Vs[vr][vc + 0] = vv.x; Vs[vr][vc + 1] = vv.y;
            Vs[vr][vc + 2] = vv.z; Vs[vr][vc + 3] = vv.w;
        }
        __syncthreads();

#pragma unroll
        for (int kk = 0; kk < 16; kk++) {
            float4 av0 = *(const float4*)&Ps[kk][ty * 8];
            float4 av1 = *(const float4*)&Ps[kk][ty * 8 + 4];
            float4 bv0 = *(const float4*)&Vs[kk][tx * 8];
            float4 bv1 = *(const float4*)&Vs[kk][tx * 8 + 4];
            float av[8] = {av0.x, av0.y, av0.z, av0.w, av1.x, av1.y, av1.z, av1.w};
            float bv[8] = {bv0.x, bv0.y, bv0.z, bv0.w, bv1.x, bv1.y, bv1.z, bv1.w};
#pragma unroll
            for (int i = 0; i < 8; i++)
#pragma unroll
                for (int j = 0; j < 8; j++) acc[i][j] += av[i] * bv[j];
        }
        __syncthreads();
    }

#pragma unroll
    for (int i = 0; i < 8; i++) {
        int row = by * 128 + ty * 8 + i;
#pragma unroll
        for (int j = 0; j < 8; j++) {
            g_attno[(size_t)row * (NHEAD * HD) + h * HD + tx * 8 + j] = acc[i][j];
        }
    }
}

// ---------------------------------------------------------------------------
// kernel_launch
// ---------------------------------------------------------------------------
extern "C" void kernel_launch(void* const* d_in, const int* in_sizes, int n_in,
                              void* d_out, int out_size)
{
    const float* hidden      = (const float*)d_in[0];
    const float* embeds      = (const float*)d_in[1];
    const float* amask       = (const float*)d_in[2];
    const float* fc_w        = (const float*)d_in[3];
    const float* fc_b        = (const float*)d_in[4];
    const float* in_norm_w   = (const float*)d_in[5];
    const float* q_w         = (const float*)d_in[6];
    const float* k_w         = (const float*)d_in[7];
    const float* v_w         = (const float*)d_in[8];
    const float* o_w         = (const float*)d_in[9];
    const float* post_norm_w = (const float*)d_in[10];
    const float* gate_w      = (const float*)d_in[11];
    const float* up_w        = (const float*)d_in[12];
    const float* down_w      = (const float*)d_in[13];
    const int* pos           = (const int*)d_in[14];
    float* out = (float*)d_out;

    void *px, *ph, *pq, *pk, *pv, *pattn, *px2, *ph2, *pgate, *pact;
    cudaGetSymbolAddress(&px, g_x);
    cudaGetSymbolAddress(&ph, g_h);
    cudaGetSymbolAddress(&pq, g_q);
    cudaGetSymbolAddress(&pk, g_k);
    cudaGetSymbolAddress(&pv, g_v);
    cudaGetSymbolAddress(&pattn, g_attno);
    cudaGetSymbolAddress(&px2, g_x2);
    cudaGetSymbolAddress(&ph2, g_h2);
    cudaGetSymbolAddress(&pgate, g_gate);
    cudaGetSymbolAddress(&pact, g_act);

#define GETB(sym) \
    void *sym##_ph, *sym##_pl; \
    cudaGetSymbolAddress(&sym##_ph, sym##_h); \
    cudaGetSymbolAddress(&sym##_pl, sym##_l);
    GETB(g_cat) GETB(g_hb) GETB(g_atb) GETB(g_h2b) GETB(g_actb)
    GETB(g_fcw) GETB(g_qw) GETB(g_kw) GETB(g_vw) GETB(g_ow)
    GETB(g_gw) GETB(g_uw) GETB(g_dw)
#undef GETB

    cudaFuncSetAttribute(tgemm<0>, cudaFuncAttributeMaxDynamicSharedMemorySize, TG_SMEM);
    cudaFuncSetAttribute(tgemm<1>, cudaFuncAttributeMaxDynamicSharedMemorySize, TG_SMEM);
    cudaFuncSetAttribute(tgemm<2>, cudaFuncAttributeMaxDynamicSharedMemorySize, TG_SMEM);
    cudaFuncSetAttribute(tgemm<3>, cudaFuncAttributeMaxDynamicSharedMemorySize, TG_SMEM);

#define SPLIT(srcp, sym, nelem) \
    split_kernel<<<(int)((size_t)(nelem) / 1024), 256>>>( \
        (const float*)(srcp), (__nv_bfloat16*)sym##_ph, (__nv_bfloat16*)sym##_pl)

    // weight splits
    SPLIT(fc_w,   g_fcw, (size_t)4096 * 8192);
    SPLIT(q_w,    g_qw,  (size_t)4096 * 4096);
    SPLIT(k_w,    g_kw,  (size_t)1024 * 4096);
    SPLIT(v_w,    g_vw,  (size_t)1024 * 4096);
    SPLIT(o_w,    g_ow,  (size_t)4096 * 4096);
    SPLIT(gate_w, g_gw,  (size_t)11008 * 4096);
    SPLIT(up_w,   g_uw,  (size_t)11008 * 4096);
    SPLIT(down_w, g_dw,  (size_t)4096 * 11008);

    // 1. concat + split
    concat_split_kernel<<<(S_LEN * 2048) / 256, 256>>>(embeds, hidden);

    // 2. fc: x = concat @ fc_w^T + fc_b   (M=2048, N=4096, K=8192)
    tgemm<1><<<dim3(32, 16), 256, TG_SMEM>>>(
        (const __nv_bfloat16*)g_cat_ph, (const __nv_bfloat16*)g_cat_pl,
        (const __nv_bfloat16*)g_fcw_ph, (const __nv_bfloat16*)g_fcw_pl,
        (float*)px, S_LEN, 4096, 8192, fc_b, nullptr);

    // 3. rmsnorm1 + split
    rmsnorm2_kernel<<<S_LEN, 256>>>((const float*)px, in_norm_w, (float*)ph);
    SPLIT(ph, g_hb, (size_t)S_LEN * 4096);

    // 4. q/k/v projections
    tgemm<0><<<dim3(32, 16), 256, TG_SMEM>>>(
        (const __nv_bfloat16*)g_hb_ph, (const __nv_bfloat16*)g_hb_pl,
        (const __nv_bfloat16*)g_qw_ph, (const __nv_bfloat16*)g_qw_pl,
        (float*)pq, S_LEN, 4096, 4096, nullptr, nullptr);
    tgemm<0><<<dim3(8, 16), 256, TG_SMEM>>>(
        (const __nv_bfloat16*)g_hb_ph, (const __nv_bfloat16*)g_hb_pl,
        (const __nv_bfloat16*)g_kw_ph, (const __nv_bfloat16*)g_kw_pl,
        (float*)pk, S_LEN, 1024, 4096, nullptr, nullptr);
    tgemm<0><<<dim3(8, 16), 256, TG_SMEM>>>(
        (const __nv_bfloat16*)g_hb_ph, (const __nv_bfloat16*)g_hb_pl,
        (const __nv_bfloat16*)g_vw_ph, (const __nv_bfloat16*)g_vw_pl,
        (float*)pv, S_LEN, 1024, 4096, nullptr, nullptr);

    // 5. RoPE
    rope_cache_kernel<<<(S_LEN * HD) / 256, 256>>>(pos);
    rope_apply_kernel<<<(S_LEN * 5120) / 256, 256>>>();

    // 6. attention
    qk_tiled<<<dim3(S_LEN / 128, S_LEN / 128, NHEAD), 256>>>(amask);
    softmax2_kernel<<<(NHEAD * S_LEN * 32) / 256, 256>>>();
    pv_gemm<<<dim3(S_LEN / 128, NHEAD), 256>>>();

    // 7. o-proj + residual
    SPLIT(pattn, g_atb, (size_t)S_LEN * 4096);
    tgemm<2><<<dim3(32, 16), 256, TG_SMEM>>>(
        (const __nv_bfloat16*)g_atb_ph, (const __nv_bfloat16*)g_atb_pl,
        (const __nv_bfloat16*)g_ow_ph, (const __nv_bfloat16*)g_ow_pl,
        (float*)px2, S_LEN, 4096, 4096, nullptr, (const float*)px);

    // 8. rmsnorm2 + split
    rmsnorm2_kernel<<<S_LEN, 256>>>((const float*)px2, post_norm_w, (float*)ph2);
    SPLIT(ph2, g_h2b, (size_t)S_LEN * 4096);

    // 9. gate
    tgemm<0><<<dim3(86, 16), 256, TG_SMEM>>>(
        (const __nv_bfloat16*)g_h2b_ph, (const __nv_bfloat16*)g_h2b_pl,
        (const __nv_bfloat16*)g_gw_ph, (const __nv_bfloat16*)g_gw_pl,
        (float*)pgate, S_LEN, I_DIM, 4096, nullptr, nullptr);

    // 10. act = silu(gate) * up
    tgemm<3><<<dim3(86, 16), 256, TG_SMEM>>>(
        (const __nv_bfloat16*)g_h2b_ph, (const __nv_bfloat16*)g_h2b_pl,
        (const __nv_bfloat16*)g_uw_ph, (const __nv_bfloat16*)g_uw_pl,
        (float*)pact, S_LEN, I_DIM, 4096, nullptr, (const float*)pgate);
    SPLIT(pact, g_actb, (size_t)S_LEN * I_DIM);

    // 11. out = act @ down_w^T + x2   (K=11008)
    tgemm<2><<<dim3(32, 16), 256, TG_SMEM>>>(
        (const __nv_bfloat16*)g_actb_ph, (const __nv_bfloat16*)g_actb_pl,
        (const __nv_bfloat16*)g_dw_ph, (const __nv_bfloat16*)g_dw_pl,
        out, S_LEN, 4096, I_DIM, nullptr, (const float*)px2);

#undef SPLIT
}

// round 14
// speedup vs baseline: 11.2646x; 1.0820x over previous
#include <cuda_runtime.h>
#include <cuda_bf16.h>
#include <cstdint>
#include <cstddef>
#include <math_constants.h>

// ---------------------------------------------------------------------------
// Problem constants (B=1)
// ---------------------------------------------------------------------------
#define S_LEN 2048
#define H_DIM 4096
#define NHEAD 32
#define NKV   8
#define HD    128
#define I_DIM 11008
#define NEGF  (-3.4028234663852886e38f)   // jnp.finfo(float32).min

// ---------------------------------------------------------------------------
// fp32 scratch
// ---------------------------------------------------------------------------
__device__ float g_x     [(size_t)S_LEN * H_DIM];
__device__ float g_h     [(size_t)S_LEN * H_DIM];
__device__ float g_q     [(size_t)S_LEN * NHEAD * HD];
__device__ float g_k     [(size_t)S_LEN * NKV * HD];
__device__ float g_v     [(size_t)S_LEN * NKV * HD];
__device__ float g_cos   [(size_t)S_LEN * HD];
__device__ float g_sin   [(size_t)S_LEN * HD];
__device__ float g_attno [(size_t)S_LEN * NHEAD * HD];
__device__ float g_x2    [(size_t)S_LEN * H_DIM];
__device__ float g_h2    [(size_t)S_LEN * H_DIM];
__device__ float g_gate  [(size_t)S_LEN * I_DIM];
__device__ float g_act   [(size_t)S_LEN * I_DIM];
__device__ float g_scores[(size_t)NHEAD * S_LEN * S_LEN];

// ---------------------------------------------------------------------------
// bf16 split scratch (hi/lo), 16B-aligned for cp.async
// ---------------------------------------------------------------------------
#define BF16BUF(name, count) \
    __device__ __align__(16) __nv_bfloat16 name##_h[count]; \
    __device__ __align__(16) __nv_bfloat16 name##_l[count];

BF16BUF(g_cat,   (size_t)S_LEN * 2 * H_DIM)
BF16BUF(g_hb,    (size_t)S_LEN * H_DIM)
BF16BUF(g_atb,   (size_t)S_LEN * NHEAD * HD)
BF16BUF(g_h2b,   (size_t)S_LEN * H_DIM)
BF16BUF(g_actb,  (size_t)S_LEN * I_DIM)
BF16BUF(g_fcw,   (size_t)H_DIM * 2 * H_DIM)
BF16BUF(g_qw,    (size_t)H_DIM * H_DIM)
BF16BUF(g_kw,    (size_t)NKV * HD * H_DIM)
BF16BUF(g_vw,    (size_t)NKV * HD * H_DIM)
BF16BUF(g_ow,    (size_t)H_DIM * H_DIM)
BF16BUF(g_gw,    (size_t)I_DIM * H_DIM)
BF16BUF(g_uw,    (size_t)I_DIM * H_DIM)
BF16BUF(g_dw,    (size_t)H_DIM * I_DIM)
// attention operands (post-rope q/k, transposed v, probabilities)
BF16BUF(g_q2b,   (size_t)S_LEN * NHEAD * HD)
BF16BUF(g_k2b,   (size_t)S_LEN * NKV * HD)
BF16BUF(g_vt,    (size_t)NKV * HD * S_LEN)            // [c=kvh*128+d, k]
BF16BUF(g_p,     (size_t)NHEAD * S_LEN * S_LEN)       // probabilities

// ---------------------------------------------------------------------------
// PTX helpers (base-target only: cp.async / ldmatrix / mma.sync)
// ---------------------------------------------------------------------------
__device__ __forceinline__ uint32_t smem_to_u32(const void* p) {
    uint32_t a;
    asm("{ .reg .u64 t; cvta.to.shared.u64 t, %1; cvt.u32.u64 %0, t; }"
        : "=r"(a) : "l"(p));
    return a;
}
#define CP16(dst_u32, src_ptr) \
    asm volatile("cp.async.cg.shared.global [%0], [%1], 16;" \
                 :: "r"(dst_u32), "l"(src_ptr) : "memory")
#define CP_COMMIT() asm volatile("cp.async.commit_group;" ::: "memory")
#define CP_WAIT1()  asm volatile("cp.async.wait_group 1;" ::: "memory")

#define LDSM4(r, addr) \
    asm volatile("ldmatrix.sync.aligned.m8n8.x4.shared.b16 {%0,%1,%2,%3}, [%4];" \
        : "=r"((r)[0]), "=r"((r)[1]), "=r"((r)[2]), "=r"((r)[3]) : "r"(addr))

#define MMA_BF16(d, a, b) \
    asm volatile("mma.sync.aligned.m16n8k16.row.col.f32.bf16.bf16.f32 " \
        "{%0,%1,%2,%3}, {%4,%5,%6,%7}, {%8,%9}, {%0,%1,%2,%3};" \
        : "+f"((d)[0]), "+f"((d)[1]), "+f"((d)[2]), "+f"((d)[3]) \
        : "r"((a)[0]), "r"((a)[1]), "r"((a)[2]), "r"((a)[3]), \
          "r"((b)[0]), "r"((b)[1]))

// Swizzled byte offset within one 128-row x 32-col bf16 tile (64B rows).
__device__ __forceinline__ uint32_t sw_off(int row, int c16) {
    int key = (row & 3) ^ ((row >> 2) & 1);
    return (uint32_t)(row * 64 + ((c16 ^ key) << 4));
}

__device__ __forceinline__ void bf16_split(float v, __nv_bfloat16& h, __nv_bfloat16& l) {
    h = __float2bfloat16(v);
    l = __float2bfloat16(v - __bfloat162float(h));
}

#define TG_STAGE 32768
#define TG_SMEM  (2 * TG_STAGE)

// ---------------------------------------------------------------------------
// MMA mainloop shared by all bf16x3 GEMMs. Base pointers pre-offset to the
// CTA tile origin; ldX in elements. Accumulates AhBh + AhBl + AlBh.
// ---------------------------------------------------------------------------
__device__ __forceinline__ void mma_mainloop(
    uint32_t sbase, int tid, int wid, int lane, int wm, int wn,
    const __nv_bfloat16* Ahb, const __nv_bfloat16* Alb, int lda,
    const __nv_bfloat16* Bhb, const __nv_bfloat16* Blb, int ldb,
    int nch, float acc[4][4][4])
{
    auto load_chunk = [&](int ch, int buf) {
        const uint32_t sb = sbase + buf * TG_STAGE;
        const int kof = ch * 32;
#pragma unroll
        for (int j = 0; j < 2; j++) {
            int cidx = tid + j * 256;
            int row = cidx >> 2;
            int c16 = cidx & 3;
            uint32_t so = sw_off(row, c16);
            size_t goA = (size_t)row * lda + kof + c16 * 8;
            size_t goB = (size_t)row * ldb + kof + c16 * 8;
            CP16(sb + so,         Ahb + goA);
            CP16(sb + 8192 + so,  Alb + goA);
            CP16(sb + 16384 + so, Bhb + goB);
            CP16(sb + 24576 + so, Blb + goB);
        }
        CP_COMMIT();
    };

    load_chunk(0, 0);

    for (int i = 0; i < nch; i++) {
        const int b = i & 1;
        if (i + 1 < nch) load_chunk(i + 1, b ^ 1);
        else CP_COMMIT();
        CP_WAIT1();
        __syncthreads();

        const uint32_t sb = sbase + b * TG_STAGE;
        const uint32_t sAh = sb, sAl = sb + 8192, sBh = sb + 16384, sBl = sb + 24576;

#pragma unroll
        for (int ks = 0; ks < 2; ks++) {
            uint32_t ah[4][4], al[4][4], bh[2][4], bl[2][4];
            const int c16 = ks * 2 + (lane >> 4);
#pragma unroll
            for (int mi = 0; mi < 4; mi++) {
                int row = wm + mi * 16 + (lane & 15);
                uint32_t off = sw_off(row, c16);
                LDSM4(ah[mi], sAh + off);
                LDSM4(al[mi], sAl + off);
            }
#pragma unroll
            for (int pi = 0; pi < 2; pi++) {
                int row = wn + pi * 16 + (lane & 15);
                uint32_t off = sw_off(row, c16);
                LDSM4(bh[pi], sBh + off);
                LDSM4(bl[pi], sBl + off);
            }
#pragma unroll
            for (int mi = 0; mi < 4; mi++) {
#pragma unroll
                for (int ni = 0; ni < 4; ni++) {
                    const int pi = ni >> 1, s = ni & 1;
                    uint32_t bfh[2] = {bh[pi][s], bh[pi][2 + s]};
                    uint32_t bfl[2] = {bl[pi][s], bl[pi][2 + s]};
                    MMA_BF16(acc[mi][ni], ah[mi], bfh);
                    MMA_BF16(acc[mi][ni], ah[mi], bfl);
                    MMA_BF16(acc[mi][ni], al[mi], bfh);
                }
            }
        }
        __syncthreads();
    }
}

// ---------------------------------------------------------------------------
// Split-bf16 NT GEMM (r10-verified structure, mainloop factored out)
//   EPI 0: none | 1: +bias | 2: +resid | 3: *silu(resid)
// ---------------------------------------------------------------------------
template <int EPI>
__global__ void __launch_bounds__(256, 1)
tgemm(const __nv_bfloat16* __restrict__ Ah, const __nv_bfloat16* __restrict__ Al,
      const __nv_bfloat16* __restrict__ Bh, const __nv_bfloat16* __restrict__ Bl,
      float* __restrict__ C, int M, int N, int K,
      const float* __restrict__ bias, const float* __restrict__ resid)
{
    extern __shared__ char smem[];
    const uint32_t sbase = smem_to_u32(smem);
    const int tid = threadIdx.x;
    const int wid = tid >> 5, lane = tid & 31;
    const int bx = blockIdx.x, by = blockIdx.y;
    const int wm = (wid & 1) * 64, wn = (wid >> 1) * 32;

    float acc[4][4][4];
#pragma unroll
    for (int mi = 0; mi < 4; mi++)
#pragma unroll
        for (int ni = 0; ni < 4; ni++)
#pragma unroll
            for (int r = 0; r < 4; r++) acc[mi][ni][r] = 0.f;

    mma_mainloop(sbase, tid, wid, lane, wm, wn,
                 Ah + (size_t)by * 128 * K, Al + (size_t)by * 128 * K, K,
                 Bh + (size_t)bx * 128 * K, Bl + (size_t)bx * 128 * K, K,
                 K >> 5, acc);

    const int g = lane >> 2;
    const int tg = (lane & 3) * 2;
    auto emit = [&](int row, int col, float v) {
        if (EPI == 1) v += bias[col];
        if (EPI == 2) v += resid[(size_t)row * N + col];
        if (EPI == 3) {
            float gg = resid[(size_t)row * N + col];
            v *= gg / (1.f + expf(-gg));
        }
        C[(size_t)row * N + col] = v;
    };
#pragma unroll
    for (int mi = 0; mi < 4; mi++)
#pragma unroll
        for (int ni = 0; ni < 4; ni++) {
            int r0 = by * 128 + wm + mi * 16 + g;
            int c0 = bx * 128 + wn + ni * 8 + tg;
            emit(r0,     c0,     acc[mi][ni][0]);
            emit(r0,     c0 + 1, acc[mi][ni][1]);
            emit(r0 + 8, c0,     acc[mi][ni][2]);
            emit(r0 + 8, c0 + 1, acc[mi][ni][3]);
        }
}

// ---------------------------------------------------------------------------
// QK^T via mma.sync bf16x3: scores[h,q,k] = dot*scale + causal/pad mask
// A = q2 split (lda 4096, col off h*128); B = k2 split (ldb 1024, off (h>>2)*128)
// ---------------------------------------------------------------------------
__global__ void __launch_bounds__(256, 1)
qk_mma(const float* __restrict__ amask)
{
    extern __shared__ char smem[];
    const uint32_t sbase = smem_to_u32(smem);
    const int tid = threadIdx.x;
    const int wid = tid >> 5, lane = tid & 31;
    const int bx = blockIdx.x, by = blockIdx.y, h = blockIdx.z;
    float* Crow = g_scores + (size_t)h * S_LEN * S_LEN;

    if (bx > by) {
        for (int i = tid; i < 128 * 128; i += 256) {
            int r = i >> 7, c = i & 127;
            Crow[(size_t)(by * 128 + r) * S_LEN + bx * 128 + c] = NEGF;
        }
        return;
    }
    const int wm = (wid & 1) * 64, wn = (wid >> 1) * 32;

    float acc[4][4][4];
#pragma unroll
    for (int mi = 0; mi < 4; mi++)
#pragma unroll
        for (int ni = 0; ni < 4; ni++)
#pragma unroll
            for (int r = 0; r < 4; r++) acc[mi][ni][r] = 0.f;

    const size_t aoff = (size_t)(by * 128) * 4096 + h * 128;
    const size_t boff = (size_t)(bx * 128) * 1024 + (h >> 2) * 128;
    mma_mainloop(sbase, tid, wid, lane, wm, wn,
                 g_q2b_h + aoff, g_q2b_l + aoff, 4096,
                 g_k2b_h + boff, g_k2b_l + boff, 1024,
                 4, acc);

    const float scale = 0.08838834764831845f;
    const int g = lane >> 2;
    const int tg = (lane & 3) * 2;
    auto emit = [&](int qq, int kk, float v) {
        float m = ((kk > qq) ? NEGF : 0.f) + ((amask[kk] > 0.5f) ? 0.f : NEGF);
        Crow[(size_t)qq * S_LEN + kk] = v * scale + m;
    };
#pragma unroll
    for (int mi = 0; mi < 4; mi++)
#pragma unroll
        for (int ni = 0; ni < 4; ni++) {
            int r0 = by * 128 + wm + mi * 16 + g;
            int c0 = bx * 128 + wn + ni * 8 + tg;
            emit(r0,     c0,     acc[mi][ni][0]);
            emit(r0,     c0 + 1, acc[mi][ni][1]);
            emit(r0 + 8, c0,     acc[mi][ni][2]);
            emit(r0 + 8, c0 + 1, acc[mi][ni][3]);
        }
}

// ---------------------------------------------------------------------------
// P @ V via mma.sync bf16x3. A = P split (lda 2048); B = Vt split (ldb 2048).
// K bounded at the causal diagonal: nch = (by+1)*4 chunks of 32.
// ---------------------------------------------------------------------------
__global__ void __launch_bounds__(256, 1)
pv_mma()
{
    extern __shared__ char smem[];
    const uint32_t sbase = smem_to_u32(smem);
    const int tid = threadIdx.x;
    const int wid = tid >> 5, lane = tid & 31;
    const int by = blockIdx.x, h = blockIdx.y;
    const int wm = (wid & 1) * 64, wn = (wid >> 1) * 32;

    float acc[4][4][4];
#pragma unroll
    for (int mi = 0; mi < 4; mi++)
#pragma unroll
        for (int ni = 0; ni < 4; ni++)
#pragma unroll
            for (int r = 0; r < 4; r++) acc[mi][ni][r] = 0.f;

    const size_t aoff = ((size_t)h * S_LEN + by * 128) * S_LEN;
    const size_t boff = (size_t)((h >> 2) * 128) * S_LEN;
    mma_mainloop(sbase, tid, wid, lane, wm, wn,
                 g_p_h + aoff, g_p_l + aoff, S_LEN,
                 g_vt_h + boff, g_vt_l + boff, S_LEN,
                 (by + 1) * 4, acc);

    const int g = lane >> 2;
    const int tg = (lane & 3) * 2;
#pragma unroll
    for (int mi = 0; mi < 4; mi++)
#pragma unroll
        for (int ni = 0; ni < 4; ni++) {
            int r0 = by * 128 + wm + mi * 16 + g;
            int c0 = wn + ni * 8 + tg;               // d within head, 0..127
            g_attno[(size_t)r0 * H_DIM + h * HD + c0]           = acc[mi][ni][0];
            g_attno[(size_t)r0 * H_DIM + h * HD + c0 + 1]       = acc[mi][ni][1];
            g_attno[(size_t)(r0 + 8) * H_DIM + h * HD + c0]     = acc[mi][ni][2];
            g_attno[(size_t)(r0 + 8) * H_DIM + h * HD + c0 + 1] = acc[mi][ni][3];
        }
}

// ---------------------------------------------------------------------------
// fp32 -> (hi, lo) bf16 split (r10-verified)
// ---------------------------------------------------------------------------
__global__ void split_kernel(const float* __restrict__ src,
                             __nv_bfloat16* __restrict__ hi,
                             __nv_bfloat16* __restrict__ lo)
{
    size_t t = (size_t)blockIdx.x * 256 + threadIdx.x;
    float4 v = ((const float4*)src)[t];
    __nv_bfloat162 h0, h1, l0, l1;
    bf16_split(v.x, h0.x, l0.x); bf16_split(v.y, h0.y, l0.y);
    bf16_split(v.z, h1.x, l1.x); bf16_split(v.w, h1.y, l1.y);
    ((__nv_bfloat162*)hi)[t * 2 + 0] = h0;
    ((__nv_bfloat162*)hi)[t * 2 + 1] = h1;
    ((__nv_bfloat162*)lo)[t * 2 + 0] = l0;
    ((__nv_bfloat162*)lo)[t * 2 + 1] = l1;
}

// concat([emb, hid]) split directly to bf16 hi/lo (r10-verified)
__global__ void concat_split_kernel(const float* __restrict__ emb,
                                    const float* __restrict__ hid)
{
    size_t t = (size_t)blockIdx.x * 256 + threadIdx.x;
    int s = (int)(t >> 11);
    int c4 = (int)(t & 2047);
    float4 v;
    if (c4 < 1024) v = ((const float4*)emb)[(size_t)s * 1024 + c4];
    else           v = ((const float4*)hid)[(size_t)s * 1024 + (c4 - 1024)];
    __nv_bfloat162 h0, h1, l0, l1;
    bf16_split(v.x, h0.x, l0.x); bf16_split(v.y, h0.y, l0.y);
    bf16_split(v.z, h1.x, l1.x); bf16_split(v.w, h1.y, l1.y);
    ((__nv_bfloat162*)g_cat_h)[t * 2 + 0] = h0;
    ((__nv_bfloat162*)g_cat_h)[t * 2 + 1] = h1;
    ((__nv_bfloat162*)g_cat_l)[t * 2 + 0] = l0;
    ((__nv_bfloat162*)g_cat_l)[t * 2 + 1] = l1;
}

// ---------------------------------------------------------------------------
// RMSNorm (r5-verified, verbatim)
// ---------------------------------------------------------------------------
__global__ void __launch_bounds__(256)
rmsnorm2_kernel(const float* __restrict__ x, const float* __restrict__ w,
                float* __restrict__ out)
{
    __shared__ float sh[256];
    int row = blockIdx.x;
    const float* xr = x + (size_t)row * H_DIM;
    float acc = 0.f;
    for (int c = threadIdx.x; c < H_DIM; c += 256) {
        float v = xr[c];
        acc += v * v;
    }
    sh[threadIdx.x] = acc;
    __syncthreads();
    for (int s2 = 128; s2 > 0; s2 >>= 1) {
        if (threadIdx.x < s2) sh[threadIdx.x] += sh[threadIdx.x + s2];
        __syncthreads();
    }
    float r = rsqrtf(sh[0] / (float)H_DIM + 1e-6f);
    for (int c = threadIdx.x; c < H_DIM; c += 256)
        out[(size_t)row * H_DIM + c] = xr[c] * r * w[c];
}

// ---------------------------------------------------------------------------
// RoPE cache (r5-verified, verbatim)
// ---------------------------------------------------------------------------
__global__ void rope_cache_kernel(const int* __restrict__ pos32)
{
    int t = blockIdx.x * 256 + threadIdx.x;
    int s = t >> 7;
    int d = t & 127;
    long long pv;
    if (pos32[1] == 1) pv = (long long)pos32[s];
    else               pv = ((const long long*)pos32)[s];
    int j = (d < 64) ? d : d - 64;
    float invf = 1.0f / powf(10000.0f, (float)(2 * j) / 128.0f);
    float ang = (float)pv * invf;
    g_cos[t] = cosf(ang);
    g_sin[t] = sinf(ang);
}

// RoPE apply: same fp32 math as the r5-verified kernel, but writes bf16 hi/lo
__global__ void rope_apply_split_kernel()
{
    int t = blockIdx.x * 256 + threadIdx.x;
    int s = t / 5120;
    int c = t % 5120;
    const float* cs = g_cos + (size_t)s * HD;
    const float* sn = g_sin + (size_t)s * HD;
    if (c < 4096) {
        int d = c & 127;
        const float* qrow = g_q + (size_t)s * 4096;
        float rh = (d < 64) ? -qrow[c + 64] : qrow[c - 64];
        float val = qrow[c] * cs[d] + rh * sn[d];
        __nv_bfloat16 hh, ll;
        bf16_split(val, hh, ll);
        g_q2b_h[(size_t)s * 4096 + c] = hh;
        g_q2b_l[(size_t)s * 4096 + c] = ll;
    } else {
        int cc = c - 4096;
        int d = cc & 127;
        const float* krow = g_k + (size_t)s * 1024;
        float rh = (d < 64) ? -krow[cc + 64] : krow[cc - 64];
        float val = krow[cc] * cs[d] + rh * sn[d];
        __nv_bfloat16 hh, ll;
        bf16_split(val, hh, ll);
        g_k2b_h[(size_t)s * 1024 + cc] = hh;
        g_k2b_l[(size_t)s * 1024 + cc] = ll;
    }
}

// ---------------------------------------------------------------------------
// V transpose + split: g_v[k, c] -> vt[c, k] (bf16 hi/lo), c = kvh*128+d
// ---------------------------------------------------------------------------
__global__ void vtrans_split_kernel()
{
    __shared__ float tile[32][33];
    const int bx = blockIdx.x;      // col tile: 0..31
    const int by = blockIdx.y;      // row tile: 0..63
    const int tx = threadIdx.x & 31;
    const int ty8 = threadIdx.x >> 5;
#pragma unroll
    for (int i = 0; i < 4; i++) {
        int ty = ty8 + i * 8;
        tile[ty][tx] = g_v[(size_t)(by * 32 + ty) * 1024 + bx * 32 + tx];
    }
    __syncthreads();
#pragma unroll
    for (int i = 0; i < 4; i++) {
        int ty = ty8 + i * 8;
        float val = tile[tx][ty];
        __nv_bfloat16 hh, ll;
        bf16_split(val, hh, ll);
        size_t o = (size_t)(bx * 32 + ty) * S_LEN + by * 32 + tx;
        g_vt_h[o] = hh;
        g_vt_l[o] = ll;
    }
}

// ---------------------------------------------------------------------------
// Softmax over the causal prefix only; writes P as bf16 hi/lo, zero-fills
// up to the 128-tile ceiling (exact r5 semantics on the valid range).
// ---------------------------------------------------------------------------
__global__ void __launch_bounds__(256)
softmax3_kernel()
{
    int gw = (blockIdx.x * 256 + threadIdx.x) >> 5;   // h*2048 + q
    int lane = threadIdx.x & 31;
    int q = gw & 2047;
    const float* row = g_scores + (size_t)gw * 2048;
    __nv_bfloat16* ph = g_p_h + (size_t)gw * 2048;
    __nv_bfloat16* pl = g_p_l + (size_t)gw * 2048;
    const int n = q + 1;
    const int kceil = ((q >> 7) + 1) << 7;

    float m = -CUDART_INF_F;
    for (int k = lane; k < n; k += 32) m = fmaxf(m, row[k]);
#pragma unroll
    for (int o = 16; o; o >>= 1) m = fmaxf(m, __shfl_xor_sync(0xffffffffu, m, o));

    float sum = 0.f;
    for (int k = lane; k < n; k += 32) sum += expf(row[k] - m);
#pragma unroll
    for (int o = 16; o; o >>= 1) sum += __shfl_xor_sync(0xffffffffu, sum, o);
    float inv = 1.f / sum;

    for (int k = lane; k < n; k += 32) {
        float p = expf(row[k] - m) * inv;
        __nv_bfloat16 hh, ll;
        bf16_split(p, hh, ll);
        ph[k] = hh;
        pl[k] = ll;
    }
    const __nv_bfloat16 z = __float2bfloat16(0.f);
    for (int k = n + lane; k < kceil; k += 32) { ph[k] = z; pl[k] = z; }
}

// ---------------------------------------------------------------------------
// kernel_launch
// ---------------------------------------------------------------------------
extern "C" void kernel_launch(void* const* d_in, const int* in_sizes, int n_in,
                              void* d_out, int out_size)
{
    const float* hidden      = (const float*)d_in[0];
    const float* embeds      = (const float*)d_in[1];
    const float* amask       = (const float*)d_in[2];
    const float* fc_w        = (const float*)d_in[3];
    const float* fc_b        = (const float*)d_in[4];
    const float* in_norm_w   = (const float*)d_in[5];
    const float* q_w         = (const float*)d_in[6];
    const float* k_w         = (const float*)d_in[7];
    const float* v_w         = (const float*)d_in[8];
    const float* o_w         = (const float*)d_in[9];
    const float* post_norm_w = (const float*)d_in[10];
    const float* gate_w      = (const float*)d_in[11];
    const float* up_w        = (const float*)d_in[12];
    const float* down_w      = (const float*)d_in[13];
    const int* pos           = (const int*)d_in[14];
    float* out = (float*)d_out;

    void *px, *ph, *pq, *pk, *pv, *pattn, *px2, *ph2, *pgate, *pact;
    cudaGetSymbolAddress(&px, g_x);
    cudaGetSymbolAddress(&ph, g_h);
    cudaGetSymbolAddress(&pq, g_q);
    cudaGetSymbolAddress(&pk, g_k);
    cudaGetSymbolAddress(&pv, g_v);
    cudaGetSymbolAddress(&pattn, g_attno);
    cudaGetSymbolAddress(&px2, g_x2);
    cudaGetSymbolAddress(&ph2, g_h2);
    cudaGetSymbolAddress(&pgate, g_gate);
    cudaGetSymbolAddress(&pact, g_act);

#define GETB(sym) \
    void *sym##_ph, *sym##_pl; \
    cudaGetSymbolAddress(&sym##_ph, sym##_h); \
    cudaGetSymbolAddress(&sym##_pl, sym##_l);
    GETB(g_cat) GETB(g_hb) GETB(g_atb) GETB(g_h2b) GETB(g_actb)
    GETB(g_fcw) GETB(g_qw) GETB(g_kw) GETB(g_vw) GETB(g_ow)
    GETB(g_gw) GETB(g_uw) GETB(g_dw)
#undef GETB

    cudaFuncSetAttribute(tgemm<0>, cudaFuncAttributeMaxDynamicSharedMemorySize, TG_SMEM);
    cudaFuncSetAttribute(tgemm<1>, cudaFuncAttributeMaxDynamicSharedMemorySize, TG_SMEM);
    cudaFuncSetAttribute(tgemm<2>, cudaFuncAttributeMaxDynamicSharedMemorySize, TG_SMEM);
    cudaFuncSetAttribute(tgemm<3>, cudaFuncAttributeMaxDynamicSharedMemorySize, TG_SMEM);
    cudaFuncSetAttribute(qk_mma, cudaFuncAttributeMaxDynamicSharedMemorySize, TG_SMEM);
    cudaFuncSetAttribute(pv_mma, cudaFuncAttributeMaxDynamicSharedMemorySize, TG_SMEM);

#define SPLIT(srcp, sym, nelem) \
    split_kernel<<<(int)((size_t)(nelem) / 1024), 256>>>( \
        (const float*)(srcp), (__nv_bfloat16*)sym##_ph, (__nv_bfloat16*)sym##_pl)

    // weight splits
    SPLIT(fc_w,   g_fcw, (size_t)4096 * 8192);
    SPLIT(q_w,    g_qw,  (size_t)4096 * 4096);
    SPLIT(k_w,    g_kw,  (size_t)1024 * 4096);
    SPLIT(v_w,    g_vw,  (size_t)1024 * 4096);
    SPLIT(o_w,    g_ow,  (size_t)4096 * 4096);
    SPLIT(gate_w, g_gw,  (size_t)11008 * 4096);
    SPLIT(up_w,   g_uw,  (size_t)11008 * 4096);
    SPLIT(down_w, g_dw,  (size_t)4096 * 11008);

    // 1. concat + split
    concat_split_kernel<<<(S_LEN * 2048) / 256, 256>>>(embeds, hidden);

    // 2. fc
    tgemm<1><<<dim3(32, 16), 256, TG_SMEM>>>(
        (const __nv_bfloat16*)g_cat_ph, (const __nv_bfloat16*)g_cat_pl,
        (const __nv_bfloat16*)g_fcw_ph, (const __nv_bfloat16*)g_fcw_pl,
        (float*)px, S_LEN, 4096, 8192, fc_b, nullptr);

    // 3. rmsnorm1 + split
    rmsnorm2_kernel<<<S_LEN, 256>>>((const float*)px, in_norm_w, (float*)ph);
    SPLIT(ph, g_hb, (size_t)S_LEN * 4096);

    // 4. q/k/v projections
    tgemm<0><<<dim3(32, 16), 256, TG_SMEM>>>(
        (const __nv_bfloat16*)g_hb_ph, (const __nv_bfloat16*)g_hb_pl,
        (const __nv_bfloat16*)g_qw_ph, (const __nv_bfloat16*)g_qw_pl,
        (float*)pq, S_LEN, 4096, 4096, nullptr, nullptr);
    tgemm<0><<<dim3(8, 16), 256, TG_SMEM>>>(
        (const __nv_bfloat16*)g_hb_ph, (const __nv_bfloat16*)g_hb_pl,
        (const __nv_bfloat16*)g_kw_ph, (const __nv_bfloat16*)g_kw_pl,
        (float*)pk, S_LEN, 1024, 4096, nullptr, nullptr);
    tgemm<0><<<dim3(8, 16), 256, TG_SMEM>>>(
        (const __nv_bfloat16*)g_hb_ph, (const __nv_bfloat16*)g_hb_pl,
        (const __nv_bfloat16*)g_vw_ph, (const __nv_bfloat16*)g_vw_pl,
        (float*)pv, S_LEN, 1024, 4096, nullptr, nullptr);

    // 5. RoPE (writes bf16 splits directly) + V transpose/split
    rope_cache_kernel<<<(S_LEN * HD) / 256, 256>>>(pos);
    rope_apply_split_kernel<<<(S_LEN * 5120) / 256, 256>>>();
    vtrans_split_kernel<<<dim3(32, 64), 256>>>();

    // 6. attention: mma QK^T -> bounded softmax (bf16 P) -> mma PV
    qk_mma<<<dim3(S_LEN / 128, S_LEN / 128, NHEAD), 256, TG_SMEM>>>(amask);
    softmax3_kernel<<<(NHEAD * S_LEN * 32) / 256, 256>>>();
    pv_mma<<<dim3(S_LEN / 128, NHEAD), 256, TG_SMEM>>>();

    // 7. o-proj + residual
    SPLIT(pattn, g_atb, (size_t)S_LEN * 4096);
    tgemm<2><<<dim3(32, 16), 256, TG_SMEM>>>(
        (const __nv_bfloat16*)g_atb_ph, (const __nv_bfloat16*)g_atb_pl,
        (const __nv_bfloat16*)g_ow_ph, (const __nv_bfloat16*)g_ow_pl,
        (float*)px2, S_LEN, 4096, 4096, nullptr, (const float*)px);

    // 8. rmsnorm2 + split
    rmsnorm2_kernel<<<S_LEN, 256>>>((const float*)px2, post_norm_w, (float*)ph2);
    SPLIT(ph2, g_h2b, (size_t)S_LEN * 4096);

    // 9. gate
    tgemm<0><<<dim3(86, 16), 256, TG_SMEM>>>(
        (const __nv_bfloat16*)g_h2b_ph, (const __nv_bfloat16*)g_h2b_pl,
        (const __nv_bfloat16*)g_gw_ph, (const __nv_bfloat16*)g_gw_pl,
        (float*)pgate, S_LEN, I_DIM, 4096, nullptr, nullptr);

    // 10. act = silu(gate) * up
    tgemm<3><<<dim3(86, 16), 256, TG_SMEM>>>(
        (const __nv_bfloat16*)g_h2b_ph, (const __nv_bfloat16*)g_h2b_pl,
        (const __nv_bfloat16*)g_uw_ph, (const __nv_bfloat16*)g_uw_pl,
        (float*)pact, S_LEN, I_DIM, 4096, nullptr, (const float*)pgate);
    SPLIT(pact, g_actb, (size_t)S_LEN * I_DIM);

    // 11. out = act @ down_w^T + x2
    tgemm<2><<<dim3(32, 16), 256, TG_SMEM>>>(
        (const __nv_bfloat16*)g_actb_ph, (const __nv_bfloat16*)g_actb_pl,
        (const __nv_bfloat16*)g_dw_ph, (const __nv_bfloat16*)g_dw_pl,
        out, S_LEN, 4096, I_DIM, nullptr, (const float*)px2);

#undef SPLIT
}

// round 15
// speedup vs baseline: 11.2851x; 1.0018x over previous
#include <cuda_runtime.h>
#include <cuda_bf16.h>
#include <cstdint>
#include <cstddef>
#include <math_constants.h>

// ---------------------------------------------------------------------------
// Problem constants (B=1)
// ---------------------------------------------------------------------------
#define S_LEN 2048
#define H_DIM 4096
#define NHEAD 32
#define NKV   8
#define HD    128
#define I_DIM 11008
#define NEGF  (-3.4028234663852886e38f)   // jnp.finfo(float32).min

// ---------------------------------------------------------------------------
// fp32 scratch
// ---------------------------------------------------------------------------
__device__ float g_x     [(size_t)S_LEN * H_DIM];
__device__ float g_h     [(size_t)S_LEN * H_DIM];
__device__ float g_q     [(size_t)S_LEN * NHEAD * HD];
__device__ float g_k     [(size_t)S_LEN * NKV * HD];
__device__ float g_v     [(size_t)S_LEN * NKV * HD];
__device__ float g_cos   [(size_t)S_LEN * HD];
__device__ float g_sin   [(size_t)S_LEN * HD];
__device__ float g_attno [(size_t)S_LEN * NHEAD * HD];
__device__ float g_x2    [(size_t)S_LEN * H_DIM];
__device__ float g_h2    [(size_t)S_LEN * H_DIM];
__device__ float g_gate  [(size_t)S_LEN * I_DIM];
__device__ float g_act   [(size_t)S_LEN * I_DIM];
__device__ float g_scores[(size_t)NHEAD * S_LEN * S_LEN];

// ---------------------------------------------------------------------------
// bf16 split scratch (hi/lo), 16B-aligned for cp.async
// ---------------------------------------------------------------------------
#define BF16BUF(name, count) \
    __device__ __align__(16) __nv_bfloat16 name##_h[count]; \
    __device__ __align__(16) __nv_bfloat16 name##_l[count];

BF16BUF(g_cat,   (size_t)S_LEN * 2 * H_DIM)
BF16BUF(g_hb,    (size_t)S_LEN * H_DIM)
BF16BUF(g_atb,   (size_t)S_LEN * NHEAD * HD)
BF16BUF(g_h2b,   (size_t)S_LEN * H_DIM)
BF16BUF(g_actb,  (size_t)S_LEN * I_DIM)
BF16BUF(g_fcw,   (size_t)H_DIM * 2 * H_DIM)
BF16BUF(g_qw,    (size_t)H_DIM * H_DIM)
BF16BUF(g_kw,    (size_t)NKV * HD * H_DIM)
BF16BUF(g_vw,    (size_t)NKV * HD * H_DIM)
BF16BUF(g_ow,    (size_t)H_DIM * H_DIM)
BF16BUF(g_gw,    (size_t)I_DIM * H_DIM)
BF16BUF(g_uw,    (size_t)I_DIM * H_DIM)
BF16BUF(g_dw,    (size_t)H_DIM * I_DIM)
// attention operands (post-rope q/k, transposed v, probabilities)
BF16BUF(g_q2b,   (size_t)S_LEN * NHEAD * HD)
BF16BUF(g_k2b,   (size_t)S_LEN * NKV * HD)
BF16BUF(g_vt,    (size_t)NKV * HD * S_LEN)            // [c=kvh*128+d, k]
BF16BUF(g_p,     (size_t)NHEAD * S_LEN * S_LEN)       // probabilities

// ---------------------------------------------------------------------------
// PTX helpers (base-target only: cp.async / ldmatrix / mma.sync)
// ---------------------------------------------------------------------------
__device__ __forceinline__ uint32_t smem_to_u32(const void* p) {
    uint32_t a;
    asm("{ .reg .u64 t; cvta.to.shared.u64 t, %1; cvt.u32.u64 %0, t; }"
        : "=r"(a) : "l"(p));
    return a;
}
#define CP16(dst_u32, src_ptr) \
    asm volatile("cp.async.cg.shared.global [%0], [%1], 16;" \
                 :: "r"(dst_u32), "l"(src_ptr) : "memory")
#define CP_COMMIT() asm volatile("cp.async.commit_group;" ::: "memory")
#define CP_WAIT1()  asm volatile("cp.async.wait_group 1;" ::: "memory")

#define LDSM4(r, addr) \
    asm volatile("ldmatrix.sync.aligned.m8n8.x4.shared.b16 {%0,%1,%2,%3}, [%4];" \
        : "=r"((r)[0]), "=r"((r)[1]), "=r"((r)[2]), "=r"((r)[3]) : "r"(addr))

#define MMA_BF16(d, a, b) \
    asm volatile("mma.sync.aligned.m16n8k16.row.col.f32.bf16.bf16.f32 " \
        "{%0,%1,%2,%3}, {%4,%5,%6,%7}, {%8,%9}, {%0,%1,%2,%3};" \
        : "+f"((d)[0]), "+f"((d)[1]), "+f"((d)[2]), "+f"((d)[3]) \
        : "r"((a)[0]), "r"((a)[1]), "r"((a)[2]), "r"((a)[3]), \
          "r"((b)[0]), "r"((b)[1]))

// Swizzled byte offset within one 128-row x 32-col bf16 tile (64B rows).
__device__ __forceinline__ uint32_t sw_off(int row, int c16) {
    int key = (row & 3) ^ ((row >> 2) & 1);
    return (uint32_t)(row * 64 + ((c16 ^ key) << 4));
}

__device__ __forceinline__ void bf16_split(float v, __nv_bfloat16& h, __nv_bfloat16& l) {
    h = __float2bfloat16(v);
    l = __float2bfloat16(v - __bfloat162float(h));
}

#define TG_STAGE 32768
#define TG_SMEM  (2 * TG_STAGE)

// ---------------------------------------------------------------------------
// MMA mainloop shared by all bf16x3 GEMMs. Base pointers pre-offset to the
// CTA tile origin; ldX in elements. Accumulates AhBh + AhBl + AlBh.
// ---------------------------------------------------------------------------
__device__ __forceinline__ void mma_mainloop(
    uint32_t sbase, int tid, int wid, int lane, int wm, int wn,
    const __nv_bfloat16* Ahb, const __nv_bfloat16* Alb, int lda,
    const __nv_bfloat16* Bhb, const __nv_bfloat16* Blb, int ldb,
    int nch, float acc[4][4][4])
{
    auto load_chunk = [&](int ch, int buf) {
        const uint32_t sb = sbase + buf * TG_STAGE;
        const int kof = ch * 32;
#pragma unroll
        for (int j = 0; j < 2; j++) {
            int cidx = tid + j * 256;
            int row = cidx >> 2;
            int c16 = cidx & 3;
            uint32_t so = sw_off(row, c16);
            size_t goA = (size_t)row * lda + kof + c16 * 8;
            size_t goB = (size_t)row * ldb + kof + c16 * 8;
            CP16(sb + so,         Ahb + goA);
            CP16(sb + 8192 + so,  Alb + goA);
            CP16(sb + 16384 + so, Bhb + goB);
            CP16(sb + 24576 + so, Blb + goB);
        }
        CP_COMMIT();
    };

    load_chunk(0, 0);

    for (int i = 0; i < nch; i++) {
        const int b = i & 1;
        if (i + 1 < nch) load_chunk(i + 1, b ^ 1);
        else CP_COMMIT();
        CP_WAIT1();
        __syncthreads();

        const uint32_t sb = sbase + b * TG_STAGE;
        const uint32_t sAh = sb, sAl = sb + 8192, sBh = sb + 16384, sBl = sb + 24576;

#pragma unroll
        for (int ks = 0; ks < 2; ks++) {
            uint32_t ah[4][4], al[4][4], bh[2][4], bl[2][4];
            const int c16 = ks * 2 + (lane >> 4);
#pragma unroll
            for (int mi = 0; mi < 4; mi++) {
                int row = wm + mi * 16 + (lane & 15);
                uint32_t off = sw_off(row, c16);
                LDSM4(ah[mi], sAh + off);
                LDSM4(al[mi], sAl + off);
            }
#pragma unroll
            for (int pi = 0; pi < 2; pi++) {
                int row = wn + pi * 16 + (lane & 15);
                uint32_t off = sw_off(row, c16);
                LDSM4(bh[pi], sBh + off);
                LDSM4(bl[pi], sBl + off);
            }
#pragma unroll
            for (int mi = 0; mi < 4; mi++) {
#pragma unroll
                for (int ni = 0; ni < 4; ni++) {
                    const int pi = ni >> 1, s = ni & 1;
                    uint32_t bfh[2] = {bh[pi][s], bh[pi][2 + s]};
                    uint32_t bfl[2] = {bl[pi][s], bl[pi][2 + s]};
                    MMA_BF16(acc[mi][ni], ah[mi], bfh);
                    MMA_BF16(acc[mi][ni], ah[mi], bfl);
                    MMA_BF16(acc[mi][ni], al[mi], bfh);
                }
            }
        }
        __syncthreads();
    }
}

// ---------------------------------------------------------------------------
// Split-bf16 NT GEMM (r10-verified structure, mainloop factored out)
//   EPI 0: none | 1: +bias | 2: +resid | 3: *silu(resid)
// ---------------------------------------------------------------------------
template <int EPI>
__global__ void __launch_bounds__(256, 1)
tgemm(const __nv_bfloat16* __restrict__ Ah, const __nv_bfloat16* __restrict__ Al,
      const __nv_bfloat16* __restrict__ Bh, const __nv_bfloat16* __restrict__ Bl,
      float* __restrict__ C, int M, int N, int K,
      const float* __restrict__ bias, const float* __restrict__ resid)
{
    extern __shared__ char smem[];
    const uint32_t sbase = smem_to_u32(smem);
    const int tid = threadIdx.x;
    const int wid = tid >> 5, lane = tid & 31;
    const int bx = blockIdx.x, by = blockIdx.y;
    const int wm = (wid & 1) * 64, wn = (wid >> 1) * 32;

    float acc[4][4][4];
#pragma unroll
    for (int mi = 0; mi < 4; mi++)
#pragma unroll
        for (int ni = 0; ni < 4; ni++)
#pragma unroll
            for (int r = 0; r < 4; r++) acc[mi][ni][r] = 0.f;

    mma_mainloop(sbase, tid, wid, lane, wm, wn,
                 Ah + (size_t)by * 128 * K, Al + (size_t)by * 128 * K, K,
                 Bh + (size_t)bx * 128 * K, Bl + (size_t)bx * 128 * K, K,
                 K >> 5, acc);

    const int g = lane >> 2;
    const int tg = (lane & 3) * 2;
    auto emit = [&](int row, int col, float v) {
        if (EPI == 1) v += bias[col];
        if (EPI == 2) v += resid[(size_t)row * N + col];
        if (EPI == 3) {
            float gg = resid[(size_t)row * N + col];
            v *= gg / (1.f + expf(-gg));
        }
        C[(size_t)row * N + col] = v;
    };
#pragma unroll
    for (int mi = 0; mi < 4; mi++)
#pragma unroll
        for (int ni = 0; ni < 4; ni++) {
            int r0 = by * 128 + wm + mi * 16 + g;
            int c0 = bx * 128 + wn + ni * 8 + tg;
            emit(r0,     c0,     acc[mi][ni][0]);
            emit(r0,     c0 + 1, acc[mi][ni][1]);
            emit(r0 + 8, c0,     acc[mi][ni][2]);
            emit(r0 + 8, c0 + 1, acc[mi][ni][3]);
        }
}

// ---------------------------------------------------------------------------
// QK^T via mma.sync bf16x3: scores[h,q,k] = dot*scale + causal/pad mask
// A = q2 split (lda 4096, col off h*128); B = k2 split (ldb 1024, off (h>>2)*128)
// ---------------------------------------------------------------------------
__global__ void __launch_bounds__(256, 1)
qk_mma(const float* __restrict__ amask)
{
    extern __shared__ char smem[];
    const uint32_t sbase = smem_to_u32(smem);
    const int tid = threadIdx.x;
    const int wid = tid >> 5, lane = tid & 31;
    const int bx = blockIdx.x, by = blockIdx.y, h = blockIdx.z;
    float* Crow = g_scores + (size_t)h * S_LEN * S_LEN;

    if (bx > by) {
        for (int i = tid; i < 128 * 128; i += 256) {
            int r = i >> 7, c = i & 127;
            Crow[(size_t)(by * 128 + r) * S_LEN + bx * 128 + c] = NEGF;
        }
        return;
    }
    const int wm = (wid & 1) * 64, wn = (wid >> 1) * 32;

    float acc[4][4][4];
#pragma unroll
    for (int mi = 0; mi < 4; mi++)
#pragma unroll
        for (int ni = 0; ni < 4; ni++)
#pragma unroll
            for (int r = 0; r < 4; r++) acc[mi][ni][r] = 0.f;

    const size_t aoff = (size_t)(by * 128) * 4096 + h * 128;
    const size_t boff = (size_t)(bx * 128) * 1024 + (h >> 2) * 128;
    mma_mainloop(sbase, tid, wid, lane, wm, wn,
                 g_q2b_h + aoff, g_q2b_l + aoff, 4096,
                 g_k2b_h + boff, g_k2b_l + boff, 1024,
                 4, acc);

    const float scale = 0.08838834764831845f;
    const int g = lane >> 2;
    const int tg = (lane & 3) * 2;
    auto emit = [&](int qq, int kk, float v) {
        float m = ((kk > qq) ? NEGF : 0.f) + ((amask[kk] > 0.5f) ? 0.f : NEGF);
        Crow[(size_t)qq * S_LEN + kk] = v * scale + m;
    };
#pragma unroll
    for (int mi = 0; mi < 4; mi++)
#pragma unroll
        for (int ni = 0; ni < 4; ni++) {
            int r0 = by * 128 + wm + mi * 16 + g;
            int c0 = bx * 128 + wn + ni * 8 + tg;
            emit(r0,     c0,     acc[mi][ni][0]);
            emit(r0,     c0 + 1, acc[mi][ni][1]);
            emit(r0 + 8, c0,     acc[mi][ni][2]);
            emit(r0 + 8, c0 + 1, acc[mi][ni][3]);
        }
}

// ---------------------------------------------------------------------------
// P @ V via mma.sync bf16x3. A = P split (lda 2048); B = Vt split (ldb 2048).
// K bounded at the causal diagonal: nch = (by+1)*4 chunks of 32.
// ---------------------------------------------------------------------------
__global__ void __launch_bounds__(256, 1)
pv_mma()
{
    extern __shared__ char smem[];
    const uint32_t sbase = smem_to_u32(smem);
    const int tid = threadIdx.x;
    const int wid = tid >> 5, lane = tid & 31;
    const int by = blockIdx.x, h = blockIdx.y;
    const int wm = (wid & 1) * 64, wn = (wid >> 1) * 32;

    float acc[4][4][4];
#pragma unroll
    for (int mi = 0; mi < 4; mi++)
#pragma unroll
        for (int ni = 0; ni < 4; ni++)
#pragma unroll
            for (int r = 0; r < 4; r++) acc[mi][ni][r] = 0.f;

    const size_t aoff = ((size_t)h * S_LEN + by * 128) * S_LEN;
    const size_t boff = (size_t)((h >> 2) * 128) * S_LEN;
    mma_mainloop(sbase, tid, wid, lane, wm, wn,
                 g_p_h + aoff, g_p_l + aoff, S_LEN,
                 g_vt_h + boff, g_vt_l + boff, S_LEN,
                 (by + 1) * 4, acc);

    const int g = lane >> 2;
    const int tg = (lane & 3) * 2;
#pragma unroll
    for (int mi = 0; mi < 4; mi++)
#pragma unroll
        for (int ni = 0; ni < 4; ni++) {
            int r0 = by * 128 + wm + mi * 16 + g;
            int c0 = wn + ni * 8 + tg;               // d within head, 0..127
            g_attno[(size_t)r0 * H_DIM + h * HD + c0]           = acc[mi][ni][0];
            g_attno[(size_t)r0 * H_DIM + h * HD + c0 + 1]       = acc[mi][ni][1];
            g_attno[(size_t)(r0 + 8) * H_DIM + h * HD + c0]     = acc[mi][ni][2];
            g_attno[(size_t)(r0 + 8) * H_DIM + h * HD + c0 + 1] = acc[mi][ni][3];
        }
}

// ---------------------------------------------------------------------------
// fp32 -> (hi, lo) bf16 split (r10-verified)
// ---------------------------------------------------------------------------
__global__ void split_kernel(const float* __restrict__ src,
                             __nv_bfloat16* __restrict__ hi,
                             __nv_bfloat16* __restrict__ lo)
{
    size_t t = (size_t)blockIdx.x * 256 + threadIdx.x;
    float4 v = ((const float4*)src)[t];
    __nv_bfloat162 h0, h1, l0, l1;
    bf16_split(v.x, h0.x, l0.x); bf16_split(v.y, h0.y, l0.y);
    bf16_split(v.z, h1.x, l1.x); bf16_split(v.w, h1.y, l1.y);
    ((__nv_bfloat162*)hi)[t * 2 + 0] = h0;
    ((__nv_bfloat162*)hi)[t * 2 + 1] = h1;
    ((__nv_bfloat162*)lo)[t * 2 + 0] = l0;
    ((__nv_bfloat162*)lo)[t * 2 + 1] = l1;
}

// concat([emb, hid]) split directly to bf16 hi/lo (r10-verified)
__global__ void concat_split_kernel(const float* __restrict__ emb,
                                    const float* __restrict__ hid)
{
    size_t t = (size_t)blockIdx.x * 256 + threadIdx.x;
    int s = (int)(t >> 11);
    int c4 = (int)(t & 2047);
    float4 v;
    if (c4 < 1024) v = ((const float4*)emb)[(size_t)s * 1024 + c4];
    else           v = ((const float4*)hid)[(size_t)s * 1024 + (c4 - 1024)];
    __nv_bfloat162 h0, h1, l0, l1;
    bf16_split(v.x, h0.x, l0.x); bf16_split(v.y, h0.y, l0.y);
    bf16_split(v.z, h1.x, l1.x); bf16_split(v.w, h1.y, l1.y);
    ((__nv_bfloat162*)g_cat_h)[t * 2 + 0] = h0;
    ((__nv_bfloat162*)g_cat_h)[t * 2 + 1] = h1;
    ((__nv_bfloat162*)g_cat_l)[t * 2 + 0] = l0;
    ((__nv_bfloat162*)g_cat_l)[t * 2 + 1] = l1;
}

// ---------------------------------------------------------------------------
// RMSNorm (r5-verified, verbatim)
// ---------------------------------------------------------------------------
__global__ void __launch_bounds__(256)
rmsnorm2_kernel(const float* __restrict__ x, const float* __restrict__ w,
                float* __restrict__ out)
{
    __shared__ float sh[256];
    int row = blockIdx.x;
    const float* xr = x + (size_t)row * H_DIM;
    float acc = 0.f;
    for (int c = threadIdx.x; c < H_DIM; c += 256) {
        float v = xr[c];
        acc += v * v;
    }
    sh[threadIdx.x] = acc;
    __syncthreads();
    for (int s2 = 128; s2 > 0; s2 >>= 1) {
        if (threadIdx.x < s2) sh[threadIdx.x] += sh[threadIdx.x + s2];
        __syncthreads();
    }
    float r = rsqrtf(sh[0] / (float)H_DIM + 1e-6f);
    for (int c = threadIdx.x; c < H_DIM; c += 256)
        out[(size_t)row * H_DIM + c] = xr[c] * r * w[c];
}

// ---------------------------------------------------------------------------
// RoPE cache (r5-verified, verbatim)
// ---------------------------------------------------------------------------
__global__ void rope_cache_kernel(const int* __restrict__ pos32)
{
    int t = blockIdx.x * 256 + threadIdx.x;
    int s = t >> 7;
    int d = t & 127;
    long long pv;
    if (pos32[1] == 1) pv = (long long)pos32[s];
    else               pv = ((const long long*)pos32)[s];
    int j = (d < 64) ? d : d - 64;
    float invf = 1.0f / powf(10000.0f, (float)(2 * j) / 128.0f);
    float ang = (float)pv * invf;
    g_cos[t] = cosf(ang);
    g_sin[t] = sinf(ang);
}

// RoPE apply: same fp32 math as the r5-verified kernel, but writes bf16 hi/lo
__global__ void rope_apply_split_kernel()
{
    int t = blockIdx.x * 256 + threadIdx.x;
    int s = t / 5120;
    int c = t % 5120;
    const float* cs = g_cos + (size_t)s * HD;
    const float* sn = g_sin + (size_t)s * HD;
    if (c < 4096) {
        int d = c & 127;
        const float* qrow = g_q + (size_t)s * 4096;
        float rh = (d < 64) ? -qrow[c + 64] : qrow[c - 64];
        float val = qrow[c] * cs[d] + rh * sn[d];
        __nv_bfloat16 hh, ll;
        bf16_split(val, hh, ll);
        g_q2b_h[(size_t)s * 4096 + c] = hh;
        g_q2b_l[(size_t)s * 4096 + c] = ll;
    } else {
        int cc = c - 4096;
        int d = cc & 127;
        const float* krow = g_k + (size_t)s * 1024;
        float rh = (d < 64) ? -krow[cc + 64] : krow[cc - 64];
        float val = krow[cc] * cs[d] + rh * sn[d];
        __nv_bfloat16 hh, ll;
        bf16_split(val, hh, ll);
        g_k2b_h[(size_t)s * 1024 + cc] = hh;
        g_k2b_l[(size_t)s * 1024 + cc] = ll;
    }
}

// ---------------------------------------------------------------------------
// V transpose + split: g_v[k, c] -> vt[c, k] (bf16 hi/lo), c = kvh*128+d
// ---------------------------------------------------------------------------
__global__ void vtrans_split_kernel()
{
    __shared__ float tile[32][33];
    const int bx = blockIdx.x;      // col tile: 0..31
    const int by = blockIdx.y;      // row tile: 0..63
    const int tx = threadIdx.x & 31;
    const int ty8 = threadIdx.x >> 5;
#pragma unroll
    for (int i = 0; i < 4; i++) {
        int ty = ty8 + i * 8;
        tile[ty][tx] = g_v[(size_t)(by * 32 + ty) * 1024 + bx * 32 + tx];
    }
    __syncthreads();
#pragma unroll
    for (int i = 0; i < 4; i++) {
        int ty = ty8 + i * 8;
        float val = tile[tx][ty];
        __nv_bfloat16 hh, ll;
        bf16_split(val, hh, ll);
        size_t o = (size_t)(bx * 32 + ty) * S_LEN + by * 32 + tx;
        g_vt_h[o] = hh;
        g_vt_l[o] = ll;
    }
}

// ---------------------------------------------------------------------------
// Softmax over the causal prefix only; writes P as bf16 hi/lo, zero-fills
// up to the 128-tile ceiling (exact r5 semantics on the valid range).
// ---------------------------------------------------------------------------
__global__ void __launch_bounds__(256)
softmax3_kernel()
{
    int gw = (blockIdx.x * 256 + threadIdx.x) >> 5;   // h*2048 + q
    int lane = threadIdx.x & 31;
    int q = gw & 2047;
    const float* row = g_scores + (size_t)gw * 2048;
    __nv_bfloat16* ph = g_p_h + (size_t)gw * 2048;
    __nv_bfloat16* pl = g_p_l + (size_t)gw * 2048;
    const int n = q + 1;
    const int kceil = ((q >> 7) + 1) << 7;

    float m = -CUDART_INF_F;
    for (int k = lane; k < n; k += 32) m = fmaxf(m, row[k]);
#pragma unroll
    for (int o = 16; o; o >>= 1) m = fmaxf(m, __shfl_xor_sync(0xffffffffu, m, o));

    float sum = 0.f;
    for (int k = lane; k < n; k += 32) sum += expf(row[k] - m);
#pragma unroll
    for (int o = 16; o; o >>= 1) sum += __shfl_xor_sync(0xffffffffu, sum, o);
    float inv = 1.f / sum;

    for (int k = lane; k < n; k += 32) {
        float p = expf(row[k] - m) * inv;
        __nv_bfloat16 hh, ll;
        bf16_split(p, hh, ll);
        ph[k] = hh;
        pl[k] = ll;
    }
    const __nv_bfloat16 z = __float2bfloat16(0.f);
    for (int k = n + lane; k < kceil; k += 32) { ph[k] = z; pl[k] = z; }
}

// ---------------------------------------------------------------------------
// kernel_launch
// ---------------------------------------------------------------------------
extern "C" void kernel_launch(void* const* d_in, const int* in_sizes, int n_in,
                              void* d_out, int out_size)
{
    const float* hidden      = (const float*)d_in[0];
    const float* embeds      = (const float*)d_in[1];
    const float* amask       = (const float*)d_in[2];
    const float* fc_w        = (const float*)d_in[3];
    const float* fc_b        = (const float*)d_in[4];
    const float* in_norm_w   = (const float*)d_in[5];
    const float* q_w         = (const float*)d_in[6];
    const float* k_w         = (const float*)d_in[7];
    const float* v_w         = (const float*)d_in[8];
    const float* o_w         = (const float*)d_in[9];
    const float* post_norm_w = (const float*)d_in[10];
    const float* gate_w      = (const float*)d_in[11];
    const float* up_w        = (const float*)d_in[12];
    const float* down_w      = (const float*)d_in[13];
    const int* pos           = (const int*)d_in[14];
    float* out = (float*)d_out;

    void *px, *ph, *pq, *pk, *pv, *pattn, *px2, *ph2, *pgate, *pact;
    cudaGetSymbolAddress(&px, g_x);
    cudaGetSymbolAddress(&ph, g_h);
    cudaGetSymbolAddress(&pq, g_q);
    cudaGetSymbolAddress(&pk, g_k);
    cudaGetSymbolAddress(&pv, g_v);
    cudaGetSymbolAddress(&pattn, g_attno);
    cudaGetSymbolAddress(&px2, g_x2);
    cudaGetSymbolAddress(&ph2, g_h2);
    cudaGetSymbolAddress(&pgate, g_gate);
    cudaGetSymbolAddress(&pact, g_act);

#define GETB(sym) \
    void *sym##_ph, *sym##_pl; \
    cudaGetSymbolAddress(&sym##_ph, sym##_h); \
    cudaGetSymbolAddress(&sym##_pl, sym##_l);
    GETB(g_cat) GETB(g_hb) GETB(g_atb) GETB(g_h2b) GETB(g_actb)
    GETB(g_fcw) GETB(g_qw) GETB(g_kw) GETB(g_vw) GETB(g_ow)
    GETB(g_gw) GETB(g_uw) GETB(g_dw)
#undef GETB

    cudaFuncSetAttribute(tgemm<0>, cudaFuncAttributeMaxDynamicSharedMemorySize, TG_SMEM);
    cudaFuncSetAttribute(tgemm<1>, cudaFuncAttributeMaxDynamicSharedMemorySize, TG_SMEM);
    cudaFuncSetAttribute(tgemm<2>, cudaFuncAttributeMaxDynamicSharedMemorySize, TG_SMEM);
    cudaFuncSetAttribute(tgemm<3>, cudaFuncAttributeMaxDynamicSharedMemorySize, TG_SMEM);
    cudaFuncSetAttribute(qk_mma, cudaFuncAttributeMaxDynamicSharedMemorySize, TG_SMEM);
    cudaFuncSetAttribute(pv_mma, cudaFuncAttributeMaxDynamicSharedMemorySize, TG_SMEM);

#define SPLIT(srcp, sym, nelem) \
    split_kernel<<<(int)((size_t)(nelem) / 1024), 256>>>( \
        (const float*)(srcp), (__nv_bfloat16*)sym##_ph, (__nv_bfloat16*)sym##_pl)

    // weight splits
    SPLIT(fc_w,   g_fcw, (size_t)4096 * 8192);
    SPLIT(q_w,    g_qw,  (size_t)4096 * 4096);
    SPLIT(k_w,    g_kw,  (size_t)1024 * 4096);
    SPLIT(v_w,    g_vw,  (size_t)1024 * 4096);
    SPLIT(o_w,    g_ow,  (size_t)4096 * 4096);
    SPLIT(gate_w, g_gw,  (size_t)11008 * 4096);
    SPLIT(up_w,   g_uw,  (size_t)11008 * 4096);
    SPLIT(down_w, g_dw,  (size_t)4096 * 11008);

    // 1. concat + split
    concat_split_kernel<<<(S_LEN * 2048) / 256, 256>>>(embeds, hidden);

    // 2. fc
    tgemm<1><<<dim3(32, 16), 256, TG_SMEM>>>(
        (const __nv_bfloat16*)g_cat_ph, (const __nv_bfloat16*)g_cat_pl,
        (const __nv_bfloat16*)g_fcw_ph, (const __nv_bfloat16*)g_fcw_pl,
        (float*)px, S_LEN, 4096, 8192, fc_b, nullptr);

    // 3. rmsnorm1 + split
    rmsnorm2_kernel<<<S_LEN, 256>>>((const float*)px, in_norm_w, (float*)ph);
    SPLIT(ph, g_hb, (size_t)S_LEN * 4096);

    // 4. q/k/v projections
    tgemm<0><<<dim3(32, 16), 256, TG_SMEM>>>(
        (const __nv_bfloat16*)g_hb_ph, (const __nv_bfloat16*)g_hb_pl,
        (const __nv_bfloat16*)g_qw_ph, (const __nv_bfloat16*)g_qw_pl,
        (float*)pq, S_LEN, 4096, 4096, nullptr, nullptr);
    tgemm<0><<<dim3(8, 16), 256, TG_SMEM>>>(
        (const __nv_bfloat16*)g_hb_ph, (const __nv_bfloat16*)g_hb_pl,
        (const __nv_bfloat16*)g_kw_ph, (const __nv_bfloat16*)g_kw_pl,
        (float*)pk, S_LEN, 1024, 4096, nullptr, nullptr);
    tgemm<0><<<dim3(8, 16), 256, TG_SMEM>>>(
        (const __nv_bfloat16*)g_hb_ph, (const __nv_bfloat16*)g_hb_pl,
        (const __nv_bfloat16*)g_vw_ph, (const __nv_bfloat16*)g_vw_pl,
        (float*)pv, S_LEN, 1024, 4096, nullptr, nullptr);

    // 5. RoPE (writes bf16 splits directly) + V transpose/split
    rope_cache_kernel<<<(S_LEN * HD) / 256, 256>>>(pos);
    rope_apply_split_kernel<<<(S_LEN * 5120) / 256, 256>>>();
    vtrans_split_kernel<<<dim3(32, 64), 256>>>();

    // 6. attention: mma QK^T -> bounded softmax (bf16 P) -> mma PV
    qk_mma<<<dim3(S_LEN / 128, S_LEN / 128, NHEAD), 256, TG_SMEM>>>(amask);
    softmax3_kernel<<<(NHEAD * S_LEN * 32) / 256, 256>>>();
    pv_mma<<<dim3(S_LEN / 128, NHEAD), 256, TG_SMEM>>>();

    // 7. o-proj + residual
    SPLIT(pattn, g_atb, (size_t)S_LEN * 4096);
    tgemm<2><<<dim3(32, 16), 256, TG_SMEM>>>(
        (const __nv_bfloat16*)g_atb_ph, (const __nv_bfloat16*)g_atb_pl,
        (const __nv_bfloat16*)g_ow_ph, (const __nv_bfloat16*)g_ow_pl,
        (float*)px2, S_LEN, 4096, 4096, nullptr, (const float*)px);

    // 8. rmsnorm2 + split
    rmsnorm2_kernel<<<S_LEN, 256>>>((const float*)px2, post_norm_w, (float*)ph2);
    SPLIT(ph2, g_h2b, (size_t)S_LEN * 4096);

    // 9. gate
    tgemm<0><<<dim3(86, 16), 256, TG_SMEM>>>(
        (const __nv_bfloat16*)g_h2b_ph, (const __nv_bfloat16*)g_h2b_pl,
        (const __nv_bfloat16*)g_gw_ph, (const __nv_bfloat16*)g_gw_pl,
        (float*)pgate, S_LEN, I_DIM, 4096, nullptr, nullptr);

    // 10. act = silu(gate) * up
    tgemm<3><<<dim3(86, 16), 256, TG_SMEM>>>(
        (const __nv_bfloat16*)g_h2b_ph, (const __nv_bfloat16*)g_h2b_pl,
        (const __nv_bfloat16*)g_uw_ph, (const __nv_bfloat16*)g_uw_pl,
        (float*)pact, S_LEN, I_DIM, 4096, nullptr, (const float*)pgate);
    SPLIT(pact, g_actb, (size_t)S_LEN * I_DIM);

    // 11. out = act @ down_w^T + x2
    tgemm<2><<<dim3(32, 16), 256, TG_SMEM>>>(
        (const __nv_bfloat16*)g_actb_ph, (const __nv_bfloat16*)g_actb_pl,
        (const __nv_bfloat16*)g_dw_ph, (const __nv_bfloat16*)g_dw_pl,
        out, S_LEN, 4096, I_DIM, nullptr, (const float*)px2);

#undef SPLIT
}